// round 11
// baseline (speedup 1.0000x reference)
#include <cuda_runtime.h>
#include <cuda_bf16.h>
#include <math.h>
#include <stdint.h>

// ---------------- problem constants ----------------
#define BB   4
#define TT   512
#define DM   1024
#define HH   16
#define DH   64
#define FF   2048
#define EE   8
#define NTOK 2048
#define EPSL 1e-5f

// GEMM tiling
#define BM 128
#define BN 128
#define BKT 32
#define AS_STRIDE 36     // 32+4 pad: fragment reads conflict-free (4g+tig)
#define BS_STRIDE 136
#define NSTAGE 3
#define A_ELEMS (BM * AS_STRIDE)    // 4608
#define B_ELEMS (BKT * BS_STRIDE)   // 4352
#define GEMM_SMEM (NSTAGE * (A_ELEMS + B_ELEMS) * 4)   // 107520

// pre-converted (tf32-rounded) constant pool layout, units of floats
#define PQ 1048576ull
#define WT_TOTAL (44ull * PQ)

// ---------------- static scratch ----------------
__device__ float g_wt  [WT_TOTAL];
__device__ float g_q   [NTOK * DM];
__device__ float g_k   [NTOK * DM];
__device__ float g_v   [NTOK * DM];
__device__ float g_k2  [NTOK * DM];
__device__ float g_v2  [NTOK * DM];
__device__ float g_ctx [NTOK * DM];
__device__ float g_attn[NTOK * DM];
__device__ float g_t1  [NTOK * DM];
__device__ float g_t1t [NTOK * DM];
__device__ float g_t2  [NTOK * DM];
__device__ float g_t2t [NTOK * DM];
__device__ float g_ys  [NTOK * 2 * DM];
__device__ float g_h   [(size_t)EE * NTOK * FF];
__device__ int   g_elist[EE * NTOK];
__device__ int   g_slot [EE * NTOK];
__device__ float g_egate[EE * NTOK];
__device__ int   g_ecnt [EE];
__device__ float g_imp  [EE];

// ---------------- helpers ----------------
__device__ __forceinline__ uint32_t f2tf(float f) {
    uint32_t u;
    asm("cvt.rna.tf32.f32 %0, %1;" : "=r"(u) : "f"(f));
    return u;
}
__device__ __forceinline__ float tfr(float f) { return __uint_as_float(f2tf(f)); }

__device__ __forceinline__ void mma8(float* c, const uint32_t* a, const uint32_t* b) {
    asm volatile(
        "mma.sync.aligned.m16n8k8.row.col.f32.tf32.tf32.f32 "
        "{%0,%1,%2,%3}, {%4,%5,%6,%7}, {%8,%9}, {%0,%1,%2,%3};\n"
        : "+f"(c[0]), "+f"(c[1]), "+f"(c[2]), "+f"(c[3])
        : "r"(a[0]), "r"(a[1]), "r"(a[2]), "r"(a[3]), "r"(b[0]), "r"(b[1]));
}

__device__ __forceinline__ uint32_t smem_u32(const void* p) {
    return (uint32_t)__cvta_generic_to_shared(p);
}
__device__ __forceinline__ void cp16(uint32_t dst, const void* src, bool pred) {
    int sz = pred ? 16 : 0;
    asm volatile("cp.async.cg.shared.global [%0], [%1], 16, %2;\n"
                 :: "r"(dst), "l"(src), "r"(sz) : "memory");
}
#define CP_COMMIT  asm volatile("cp.async.commit_group;\n" ::: "memory")
#define CP_WAIT1   asm volatile("cp.async.wait_group 1;\n" ::: "memory")
#define CP_WAIT0   asm volatile("cp.async.wait_group 0;\n" ::: "memory")

__device__ __forceinline__ float block_reduce_sum(float v, float* red) {
    int lane = threadIdx.x & 31, w = threadIdx.x >> 5;
    #pragma unroll
    for (int o = 16; o; o >>= 1) v += __shfl_xor_sync(0xFFFFFFFFu, v, o);
    __syncthreads();
    if (lane == 0) red[w] = v;
    __syncthreads();
    if (w == 0) {
        v = (lane < ((int)blockDim.x >> 5)) ? red[lane] : 0.0f;
        #pragma unroll
        for (int o = 16; o; o >>= 1) v += __shfl_xor_sync(0xFFFFFFFFu, v, o);
        if (lane == 0) red[0] = v;
    }
    __syncthreads();
    return red[0];
}

// ---------------- prep: tf32-round all static operands into g_wt (+ zero init) ----------------
__global__ void prep_kernel(
    const float* s0, const float* s1, const float* s2, const float* s3,
    const float* s4, const float* s5, const float* s6, const float* s7,
    const float* s8, const float* s9, const float* s10, const float* s11)
{
    if (blockIdx.x == 0 && blockIdx.y == 0 && threadIdx.x < EE) {
        g_ecnt[threadIdx.x] = 0; g_imp[threadIdx.x] = 0.0f;
    }
    int r = blockIdx.y;
    const float* src; size_t off, cnt;
    switch (r) {
        case 0:  src = s0;  off = 0;       cnt = PQ;      break;
        case 1:  src = s1;  off = PQ;      cnt = PQ;      break;
        case 2:  src = s2;  off = 2 * PQ;  cnt = PQ;      break;
        case 3:  src = s3;  off = 3 * PQ;  cnt = PQ;      break;
        case 4:  src = s4;  off = 4 * PQ;  cnt = PQ;      break;
        case 5:  src = s5;  off = 5 * PQ;  cnt = PQ;      break;
        case 6:  src = s6;  off = 6 * PQ;  cnt = PQ;      break;
        case 7:  src = s7;  off = 7 * PQ;  cnt = PQ;      break;
        case 8:  src = s8;  off = 8 * PQ;  cnt = 16 * PQ; break;
        case 9:  src = s9;  off = 24 * PQ; cnt = 16 * PQ; break;
        case 10: src = s10; off = 40 * PQ; cnt = 2 * PQ;  break;
        default: src = s11; off = 42 * PQ; cnt = 2 * PQ;  break;
    }
    const float4* sp = (const float4*)src;
    float4* dp = (float4*)(g_wt + off);
    size_t n4 = cnt >> 2;
    for (size_t i = blockIdx.x * blockDim.x + threadIdx.x; i < n4;
         i += (size_t)gridDim.x * blockDim.x) {
        float4 v = sp[i];
        v.x = tfr(v.x); v.y = tfr(v.y); v.z = tfr(v.z); v.w = tfr(v.w);
        dp[i] = v;
    }
}

// ================= tf32 MMA GEMM core (BKT=32, cp.async 3-stage) =================
// MODE 0: plain; MODE 1: moe gather+relu+round; MODE 2: moe slot-scatter; MODE 3: rounded out
template<int MODE>
__device__ __forceinline__ void gemm_core(
    const float* __restrict__ A, const float* __restrict__ W,
    const float* __restrict__ bias, float* __restrict__ C,
    int K, int N, int row0, int col0,
    const int* atoks, const int* slots, const float* gates)
{
    extern __shared__ uint32_t smp[];
    uint32_t* As = smp;
    uint32_t* Bs = smp + NSTAGE * A_ELEMS;

    const int tid  = threadIdx.x;
    const int lane = tid & 31;
    const int wid  = tid >> 5;
    const int wm   = wid >> 2;
    const int wn   = wid & 3;
    const int g    = lane >> 2;
    const int tig  = lane & 3;

    // A loader: one 128-row tile of 32 floats; thread covers half a row (16 floats)
    const int lr0 = tid >> 1;              // 0..127
    const int akq = (tid & 1) * 16;        // 0 or 16
    bool p0 = true;
    const float* a0p;
    if (MODE == 1) {
        int t0 = atoks[lr0];
        p0 = (t0 >= 0);
        a0p = A + (size_t)(p0 ? t0 : 0) * K + akq;
    } else {
        a0p = A + (size_t)(row0 + lr0) * K + akq;
    }

    // B loader: 32 rows x 128 floats; thread covers 16 floats
    const int kr = tid >> 3;               // 0..31
    const int nq = (tid & 7) * 16;         // 0..112
    const float* bp = W + (size_t)kr * N + col0 + nq;

    uint32_t sA0 = smem_u32(As) + (lr0 * AS_STRIDE + akq) * 4;
    uint32_t sB0 = smem_u32(Bs) + (kr * BS_STRIDE + nq) * 4;

    const int nk = K / BKT;

#define ISSUE(b, kti) do {                                       \
        const float* as_ = a0p + (size_t)(kti) * BKT;            \
        uint32_t ao = sA0 + (uint32_t)(b) * (A_ELEMS * 4);       \
        cp16(ao,      as_,      p0); cp16(ao + 16, as_ + 4,  p0);\
        cp16(ao + 32, as_ + 8,  p0); cp16(ao + 48, as_ + 12, p0);\
        const float* bs_ = bp + (size_t)(kti) * BKT * N;         \
        uint32_t bo = sB0 + (uint32_t)(b) * (B_ELEMS * 4);       \
        cp16(bo,      bs_,      true); cp16(bo + 16, bs_ + 4,  true);\
        cp16(bo + 32, bs_ + 8,  true); cp16(bo + 48, bs_ + 12, true);\
    } while (0)

    ISSUE(0, 0); CP_COMMIT;
    ISSUE(1, 1); CP_COMMIT;

    float acc[4][4][4];
    #pragma unroll
    for (int i = 0; i < 4; i++)
        #pragma unroll
        for (int j = 0; j < 4; j++)
            #pragma unroll
            for (int r = 0; r < 4; r++) acc[i][j][r] = 0.0f;

    int buf = 0;
    for (int kt = 0; kt < nk; kt++) {
        CP_WAIT1;
        __syncthreads();
        if (kt + 2 < nk) {
            int nb = buf + 2; if (nb >= NSTAGE) nb -= NSTAGE;
            ISSUE(nb, kt + 2);
        }
        CP_COMMIT;

        const uint32_t* Ab = As + buf * A_ELEMS;
        const uint32_t* Bb = Bs + buf * B_ELEMS;
        #pragma unroll
        for (int k8 = 0; k8 < 4; k8++) {
            uint32_t af[4][4], bf[4][2];
            const uint32_t* abase = Ab + (wm * 64 + g) * AS_STRIDE + k8 * 8 + tig;
            #pragma unroll
            for (int mt = 0; mt < 4; mt++) {
                const uint32_t* p = abase + mt * 16 * AS_STRIDE;
                af[mt][0] = p[0];
                af[mt][1] = p[8 * AS_STRIDE];
                af[mt][2] = p[4];
                af[mt][3] = p[8 * AS_STRIDE + 4];
            }
            const uint32_t* bbase = Bb + (k8 * 8 + tig) * BS_STRIDE + wn * 32 + g;
            #pragma unroll
            for (int nt = 0; nt < 4; nt++) {
                bf[nt][0] = bbase[nt * 8];
                bf[nt][1] = bbase[4 * BS_STRIDE + nt * 8];
            }
            #pragma unroll
            for (int mt = 0; mt < 4; mt++)
                #pragma unroll
                for (int nt = 0; nt < 4; nt++)
                    mma8(acc[mt][nt], af[mt], bf[nt]);
        }
        buf = (buf == NSTAGE - 1) ? 0 : buf + 1;
    }
#undef ISSUE

    #pragma unroll
    for (int mt = 0; mt < 4; mt++) {
        const int lr = wm * 64 + mt * 16 + g;
        #pragma unroll
        for (int nt = 0; nt < 4; nt++) {
            float* ac = acc[mt][nt];
            const int c = col0 + wn * 32 + nt * 8 + 2 * tig;
            const float bc0 = bias[c], bc1 = bias[c + 1];
            if (MODE == 0) {
                *(float2*)&C[(size_t)(row0 + lr) * N + c]     = make_float2(ac[0] + bc0, ac[1] + bc1);
                *(float2*)&C[(size_t)(row0 + lr + 8) * N + c] = make_float2(ac[2] + bc0, ac[3] + bc1);
            } else if (MODE == 3) {
                *(float2*)&C[(size_t)(row0 + lr) * N + c]     = make_float2(tfr(ac[0] + bc0), tfr(ac[1] + bc1));
                *(float2*)&C[(size_t)(row0 + lr + 8) * N + c] = make_float2(tfr(ac[2] + bc0), tfr(ac[3] + bc1));
            } else if (MODE == 1) {
                if (atoks[lr] >= 0)
                    *(float2*)&C[(size_t)(row0 + lr) * N + c] = make_float2(
                        tfr(fmaxf(ac[0] + bc0, 0.f)), tfr(fmaxf(ac[1] + bc1, 0.f)));
                if (atoks[lr + 8] >= 0)
                    *(float2*)&C[(size_t)(row0 + lr + 8) * N + c] = make_float2(
                        tfr(fmaxf(ac[2] + bc0, 0.f)), tfr(fmaxf(ac[3] + bc1, 0.f)));
            } else {
                int sid = slots[lr]; float gt = gates[lr];
                if (sid >= 0)
                    *(float2*)&C[(size_t)sid * DM + c] =
                        make_float2(gt * (ac[0] + bc0), gt * (ac[1] + bc1));
                sid = slots[lr + 8]; gt = gates[lr + 8];
                if (sid >= 0)
                    *(float2*)&C[(size_t)sid * DM + c] =
                        make_float2(gt * (ac[2] + bc0), gt * (ac[3] + bc1));
            }
        }
    }
}

// ---------------- GEMM wrappers ----------------
__global__ __launch_bounds__(256, 2) void proj_qkv_kernel(
    const float* A0, const float* A1, const float* A2,
    const float* W0, const float* W1, const float* W2,
    const float* b0, const float* b1, const float* b2,
    float* C0, float* C1, float* C2, int K, int N)
{
    const int z = blockIdx.z;
    const float* A = (z == 0) ? A0 : (z == 1) ? A1 : A2;
    const float* W = (z == 0) ? W0 : (z == 1) ? W1 : W2;
    const float* b = (z == 0) ? b0 : (z == 1) ? b1 : b2;
    float*       C = (z == 0) ? C0 : (z == 1) ? C1 : C2;
    gemm_core<0>(A, W, b, C, K, N, blockIdx.y * BM, blockIdx.x * BN,
                 nullptr, nullptr, nullptr);
}

__global__ __launch_bounds__(256, 2) void proj_qkvr_kernel(
    const float* A0, const float* A1, const float* A2,
    const float* W0, const float* W1, const float* W2,
    const float* b0, const float* b1, const float* b2,
    float* C0, float* C1, float* C2, int K, int N)
{
    const int z = blockIdx.z;
    const float* A = (z == 0) ? A0 : (z == 1) ? A1 : A2;
    const float* W = (z == 0) ? W0 : (z == 1) ? W1 : W2;
    const float* b = (z == 0) ? b0 : (z == 1) ? b1 : b2;
    float*       C = (z == 0) ? C0 : (z == 1) ? C1 : C2;
    gemm_core<3>(A, W, b, C, K, N, blockIdx.y * BM, blockIdx.x * BN,
                 nullptr, nullptr, nullptr);
}

// 5-way packed rounded projections (sa_q, sa_k, sa_v, ca_k, ca_v)
__global__ __launch_bounds__(256, 2) void proj_qkv5_kernel(
    const float* A0, const float* A1, const float* A2, const float* A3, const float* A4,
    const float* W0, const float* W1, const float* W2, const float* W3, const float* W4,
    const float* b0, const float* b1, const float* b2, const float* b3, const float* b4,
    float* C0, float* C1, float* C2, float* C3, float* C4, int K, int N)
{
    const int z = blockIdx.z;
    const float* A = (z == 0) ? A0 : (z == 1) ? A1 : (z == 2) ? A2 : (z == 3) ? A3 : A4;
    const float* W = (z == 0) ? W0 : (z == 1) ? W1 : (z == 2) ? W2 : (z == 3) ? W3 : W4;
    const float* b = (z == 0) ? b0 : (z == 1) ? b1 : (z == 2) ? b2 : (z == 3) ? b3 : b4;
    float*       C = (z == 0) ? C0 : (z == 1) ? C1 : (z == 2) ? C2 : (z == 3) ? C3 : C4;
    gemm_core<3>(A, W, b, C, K, N, blockIdx.y * BM, blockIdx.x * BN,
                 nullptr, nullptr, nullptr);
}

__global__ __launch_bounds__(256, 2) void moe1_kernel(
    const float* __restrict__ X, const float* __restrict__ w1,
    const float* __restrict__ b1)
{
    const int e = blockIdx.z;
    const int cnt = g_ecnt[e];
    const int row0 = blockIdx.y * BM;
    if (row0 >= cnt) return;
    __shared__ int toks[BM];
    if (threadIdx.x < BM) {
        int r = row0 + threadIdx.x;
        toks[threadIdx.x] = (r < cnt) ? g_elist[e * NTOK + r] : -1;
    }
    __syncthreads();
    gemm_core<1>(X, w1 + (size_t)e * DM * FF, b1 + e * FF,
                 g_h + (size_t)e * NTOK * FF,
                 DM, FF, row0, blockIdx.x * BN, toks, nullptr, nullptr);
}

__global__ __launch_bounds__(256, 2) void moe2_kernel(
    const float* __restrict__ w2, const float* __restrict__ b2)
{
    const int e = blockIdx.z;
    const int cnt = g_ecnt[e];
    const int row0 = blockIdx.y * BM;
    if (row0 >= cnt) return;
    __shared__ int slts[BM];
    __shared__ float gat[BM];
    if (threadIdx.x < BM) {
        int r = row0 + threadIdx.x;
        bool ok = (r < cnt);
        slts[threadIdx.x] = ok ? g_slot[e * NTOK + r] : -1;
        gat[threadIdx.x]  = ok ? g_egate[e * NTOK + r] : 0.0f;
    }
    __syncthreads();
    gemm_core<2>(g_h + (size_t)e * NTOK * FF, w2 + (size_t)e * FF * DM,
                 b2 + e * DM, g_ys,
                 FF, DM, row0, blockIdx.x * BN, nullptr, slts, gat);
}

// ---------------- tensor-core attention (512 threads, cp.async double-buffered) ----------------
#define AQT   32
#define KT2   64
#define KSTR  68
#define VSTR  72
#define KVBUF (KT2 * VSTR)                 // 4608 floats per buffer
#define SSTR  516
#define QF_ELEMS (2 * 8 * 32 * 4)          // 2048 u32
#define ATC_SMEM ((QF_ELEMS + 2 * KVBUF + AQT * SSTR) * 4)   // 111104 B

__global__ __launch_bounds__(512, 2) void attn_tc_kernel(
    const float* __restrict__ Q, const float* __restrict__ Kk,
    const float* __restrict__ V, float* __restrict__ O)
{
    extern __shared__ float am[];
    uint32_t* Qf = (uint32_t*)am;        // [2][8][32][4] fragment-major
    float* KV = am + QF_ELEMS;           // [2][KVBUF]
    float* S  = KV + 2 * KVBUF;          // [AQT][SSTR]

    const int q0  = blockIdx.x * AQT;
    const int h   = blockIdx.y;
    const int b   = blockIdx.z;
    const int tid = threadIdx.x;
    const int lane = tid & 31;
    const int wid  = tid >> 5;          // 0..15
    const int wm   = wid >> 3;          // 0..1
    const int wn   = wid & 7;           // 0..7
    const int g    = lane >> 2;         // 0..7
    const int tig  = lane & 3;          // 0..3

    const int lrow = tid >> 3;             // 0..63
    const int lc   = (tid & 7) * 8;        // 0..56
    const float* ksrc = Kk + ((size_t)(b * TT) + lrow) * DM + h * DH + lc;
    const float* vsrc = V  + ((size_t)(b * TT) + lrow) * DM + h * DH + lc;
    uint32_t kdst = smem_u32(KV) + (lrow * KSTR + lc) * 4;
    uint32_t vdst = smem_u32(KV) + (lrow * VSTR + lc) * 4;

#define ISSUE_K(bf_, kt_) do {                                         \
        const float* s_ = ksrc + (size_t)(kt_) * KT2 * DM;             \
        uint32_t d_ = kdst + (uint32_t)(bf_) * (KVBUF * 4);            \
        cp16(d_, s_, true); cp16(d_ + 16, s_ + 4, true);               \
    } while (0)
#define ISSUE_V(bf_, kt_) do {                                         \
        const float* s_ = vsrc + (size_t)(kt_) * KT2 * DM;             \
        uint32_t d_ = vdst + (uint32_t)(bf_) * (KVBUF * 4);            \
        cp16(d_, s_, true); cp16(d_ + 16, s_ + 4, true);               \
    } while (0)

    ISSUE_K(0, 0); CP_COMMIT;

    // ---- load Q into fragment-major layout ----
    for (int i = tid; i < QF_ELEMS; i += 512) {
        int r     = i & 3;
        int lane_ = (i >> 2) & 31;
        int k8    = (i >> 7) & 7;
        int wmf   = i >> 10;
        int gg = lane_ >> 2, tt = lane_ & 3;
        int row = q0 + wmf * 16 + gg + (r & 1) * 8;
        int col = k8 * 8 + tt + (r >> 1) * 4;
        float v = Q[((size_t)(b * TT + row)) * DM + h * DH + col] * 0.125f;
        Qf[i] = __float_as_uint(v);
    }

    // ---- scores ----
    int buf = 0;
    for (int kt = 0; kt < TT / KT2; kt++) {
        const bool more = (kt + 1 < TT / KT2);
        if (more) { ISSUE_K(buf ^ 1, kt + 1); CP_COMMIT; }
        if (more) { CP_WAIT1; } else { CP_WAIT0; }
        __syncthreads();

        const float* Kb = KV + buf * KVBUF;
        float c[4] = {0.f, 0.f, 0.f, 0.f};
        #pragma unroll
        for (int k8 = 0; k8 < DH / 8; k8++) {
            uint32_t af[4];
            *(uint4*)af = *(const uint4*)(Qf + ((wm * 8 + k8) * 32 + lane) * 4);
            const uint32_t* bb = (const uint32_t*)(Kb + (wn * 8 + g) * KSTR + k8 * 8 + tig);
            uint32_t bf2[2] = { bb[0], bb[4] };
            mma8(c, af, bf2);
        }
        int col = kt * KT2 + wn * 8 + 2 * tig;
        float* s0 = S + (wm * 16 + g) * SSTR + col;
        float* s1 = S + (wm * 16 + g + 8) * SSTR + col;
        s0[0] = c[0]; s0[1] = c[1];
        s1[0] = c[2]; s1[1] = c[3];
        __syncthreads();
        buf ^= 1;
    }

    ISSUE_V(0, 0); CP_COMMIT;

    // ---- softmax ----
    #pragma unroll
    for (int rr = 0; rr < 2; rr++) {
        int row = wid * 2 + rr;
        float* sr = S + row * SSTR;
        float m = -1e30f;
        for (int j = lane; j < TT; j += 32) m = fmaxf(m, sr[j]);
        #pragma unroll
        for (int o = 16; o; o >>= 1) m = fmaxf(m, __shfl_xor_sync(0xFFFFFFFFu, m, o));
        float sum = 0.0f;
        for (int j = lane; j < TT; j += 32) { float ev = __expf(sr[j] - m); sr[j] = ev; sum += ev; }
        #pragma unroll
        for (int o = 16; o; o >>= 1) sum += __shfl_xor_sync(0xFFFFFFFFu, sum, o);
        float inv = 1.0f / sum;
        for (int j = lane; j < TT; j += 32) sr[j] = tfr(sr[j] * inv);
    }

    // ---- PV ----
    float acc[4] = {0.f, 0.f, 0.f, 0.f};
    buf = 0;
    for (int vt = 0; vt < TT / KT2; vt++) {
        const bool more = (vt + 1 < TT / KT2);
        if (more) { ISSUE_V(buf ^ 1, vt + 1); CP_COMMIT; }
        if (more) { CP_WAIT1; } else { CP_WAIT0; }
        __syncthreads();

        const float* Vb = KV + buf * KVBUF;
        #pragma unroll
        for (int k8 = 0; k8 < KT2 / 8; k8++) {
            uint32_t af[4];
            const uint32_t* ab = (const uint32_t*)(S + (wm * 16 + g) * SSTR + vt * KT2 + k8 * 8 + tig);
            af[0] = ab[0]; af[1] = ab[8 * SSTR]; af[2] = ab[4]; af[3] = ab[8 * SSTR + 4];
            const uint32_t* bb = (const uint32_t*)(Vb + (k8 * 8 + tig) * VSTR + wn * 8 + g);
            uint32_t bf2[2] = { bb[0], bb[4 * VSTR] };
            mma8(acc, af, bf2);
        }
        __syncthreads();
        buf ^= 1;
    }
#undef ISSUE_K
#undef ISSUE_V

    {
        int col = h * DH + wn * 8 + 2 * tig;
        size_t r0 = (size_t)(b * TT + q0 + wm * 16 + g) * DM + col;
        size_t r1 = (size_t)(b * TT + q0 + wm * 16 + g + 8) * DM + col;
        O[r0]     = tfr(acc[0]); O[r0 + 1] = tfr(acc[1]);
        O[r1]     = tfr(acc[2]); O[r1 + 1] = tfr(acc[3]);
    }
}

// ---------------- add + layernorm (dual output) ----------------
__global__ __launch_bounds__(256) void add_ln_kernel(
    const float* __restrict__ x, const float* __restrict__ r,
    const float* __restrict__ g, const float* __restrict__ be,
    float* __restrict__ out, float* __restrict__ out_t)
{
    __shared__ float red[32];
    __shared__ float s_mean, s_rstd;
    int row = blockIdx.x, tid = threadIdx.x;
    const float* xp = x + (size_t)row * DM;
    const float* rp = r + (size_t)row * DM;
    float v[4]; float sum = 0.0f;
    #pragma unroll
    for (int i = 0; i < 4; i++) { int idx = tid + i * 256; v[i] = xp[idx] + rp[idx]; sum += v[i]; }
    sum = block_reduce_sum(sum, red);
    if (tid == 0) s_mean = sum * (1.0f / DM);
    __syncthreads();
    float mean = s_mean, vs = 0.0f;
    #pragma unroll
    for (int i = 0; i < 4; i++) { float dv = v[i] - mean; vs += dv * dv; }
    vs = block_reduce_sum(vs, red);
    if (tid == 0) s_rstd = rsqrtf(vs * (1.0f / DM) + EPSL);
    __syncthreads();
    float rs = s_rstd;
    #pragma unroll
    for (int i = 0; i < 4; i++) {
        int idx = tid + i * 256;
        float o = (v[i] - mean) * rs * g[idx] + be[idx];
        out[(size_t)row * DM + idx] = o;
        if (out_t) out_t[(size_t)row * DM + idx] = tfr(o);
    }
}

// ---------------- final add + layernorm over expert slots ----------------
__global__ __launch_bounds__(256) void add_ln_moe_kernel(
    const float* __restrict__ r, const float* __restrict__ g,
    const float* __restrict__ be, float* __restrict__ out)
{
    __shared__ float red[32];
    __shared__ float s_mean, s_rstd;
    int row = blockIdx.x, tid = threadIdx.x;
    const float* y0 = g_ys + (size_t)(row * 2) * DM;
    const float* y1 = y0 + DM;
    const float* rp = r + (size_t)row * DM;
    float v[4]; float sum = 0.0f;
    #pragma unroll
    for (int i = 0; i < 4; i++) {
        int idx = tid + i * 256;
        v[i] = y0[idx] + y1[idx] + rp[idx];
        sum += v[i];
    }
    sum = block_reduce_sum(sum, red);
    if (tid == 0) s_mean = sum * (1.0f / DM);
    __syncthreads();
    float mean = s_mean, vs = 0.0f;
    #pragma unroll
    for (int i = 0; i < 4; i++) { float dv = v[i] - mean; vs += dv * dv; }
    vs = block_reduce_sum(vs, red);
    if (tid == 0) s_rstd = rsqrtf(vs * (1.0f / DM) + EPSL);
    __syncthreads();
    float rs = s_rstd;
    #pragma unroll
    for (int i = 0; i < 4; i++) {
        int idx = tid + i * 256;
        out[(size_t)row * DM + idx] = (v[i] - mean) * rs * g[idx] + be[idx];
    }
}

// ---------------- router ----------------
__global__ __launch_bounds__(256) void router_kernel(
    const float* __restrict__ x, const float* __restrict__ rw,
    const float* __restrict__ rb)
{
    int t = blockIdx.x;
    int tid = threadIdx.x, lane = tid & 31, w = tid >> 5;
    __shared__ float logits[EE];
    const float* xp = x + (size_t)t * DM;
    float acc = 0.0f;
    for (int d = lane; d < DM; d += 32) acc += xp[d] * rw[d * EE + w];
    #pragma unroll
    for (int o = 16; o; o >>= 1) acc += __shfl_xor_sync(0xFFFFFFFFu, acc, o);
    if (lane == 0) logits[w] = acc + rb[w];
    __syncthreads();
    if (tid == 0) {
        float m = logits[0];
        #pragma unroll
        for (int e = 1; e < EE; e++) m = fmaxf(m, logits[e]);
        float p[EE], sum = 0.0f;
        #pragma unroll
        for (int e = 0; e < EE; e++) { p[e] = __expf(logits[e] - m); sum += p[e]; }
        float inv = 1.0f / sum;
        #pragma unroll
        for (int e = 0; e < EE; e++) { p[e] *= inv; atomicAdd(&g_imp[e], p[e]); }
        int i0 = 0;
        #pragma unroll
        for (int e = 1; e < EE; e++) if (p[e] > p[i0]) i0 = e;
        int i1 = (i0 == 0) ? 1 : 0;
        #pragma unroll
        for (int e = 0; e < EE; e++) if (e != i0 && p[e] > p[i1]) i1 = e;
        float g0 = p[i0], g1 = p[i1], gs = 1.0f / (g0 + g1);
        g0 *= gs; g1 *= gs;
        int pos = atomicAdd(&g_ecnt[i0], 1);
        g_elist[i0 * NTOK + pos] = t; g_egate[i0 * NTOK + pos] = g0;
        g_slot[i0 * NTOK + pos] = 2 * t;
        pos = atomicAdd(&g_ecnt[i1], 1);
        g_elist[i1 * NTOK + pos] = t; g_egate[i1 * NTOK + pos] = g1;
        g_slot[i1 * NTOK + pos] = 2 * t + 1;
    }
}

// ---------------- load-balance loss ----------------
__global__ void lb_kernel(float* __restrict__ out) {
    float lb = 0.0f;
    #pragma unroll
    for (int e = 0; e < EE; e++)
        lb += ((float)g_ecnt[e] / (float)(NTOK * 2)) * (g_imp[e] / (float)NTOK);
    out[0] = (float)EE * lb;
}

// ---------------- host launcher ----------------
extern "C" void kernel_launch(void* const* d_in, const int* in_sizes, int n_in,
                              void* d_out, int out_size)
{
    const float* tgt = (const float*)d_in[0];
    const float* mem = (const float*)d_in[1];
    const float *sa_wq, *sa_wk, *sa_wv, *sa_wo, *ca_wq, *ca_wk, *ca_wv, *ca_wo;
    const float *sa_bq, *sa_bk, *sa_bv, *sa_bo, *ca_bq, *ca_bk, *ca_bv, *ca_bo;
    const float *ln1g, *ln1b, *ln2g, *ln2b, *ln3g, *ln3b, *rw, *rb, *w1, *b1, *w2, *b2;

    if (in_sizes[5] == DM * DM) {
        sa_wq = (const float*)d_in[2];  sa_wk = (const float*)d_in[3];
        sa_wv = (const float*)d_in[4];  sa_wo = (const float*)d_in[5];
        ca_wq = (const float*)d_in[6];  ca_wk = (const float*)d_in[7];
        ca_wv = (const float*)d_in[8];  ca_wo = (const float*)d_in[9];
        sa_bq = (const float*)d_in[10]; sa_bk = (const float*)d_in[11];
        sa_bv = (const float*)d_in[12]; sa_bo = (const float*)d_in[13];
        ca_bq = (const float*)d_in[14]; ca_bk = (const float*)d_in[15];
        ca_bv = (const float*)d_in[16]; ca_bo = (const float*)d_in[17];
        ln1g = (const float*)d_in[18]; ln2g = (const float*)d_in[19]; ln3g = (const float*)d_in[20];
        ln1b = (const float*)d_in[21]; ln2b = (const float*)d_in[22]; ln3b = (const float*)d_in[23];
    } else {
        sa_wq = (const float*)d_in[2];  sa_wk = (const float*)d_in[3];
        sa_wv = (const float*)d_in[4];
        sa_bq = (const float*)d_in[5];  sa_bk = (const float*)d_in[6];
        sa_bv = (const float*)d_in[7];
        sa_wo = (const float*)d_in[8];  sa_bo = (const float*)d_in[9];
        ca_wq = (const float*)d_in[10]; ca_wk = (const float*)d_in[11];
        ca_wv = (const float*)d_in[12];
        ca_bq = (const float*)d_in[13]; ca_bk = (const float*)d_in[14];
        ca_bv = (const float*)d_in[15];
        ca_wo = (const float*)d_in[16]; ca_bo = (const float*)d_in[17];
        ln1g = (const float*)d_in[18]; ln1b = (const float*)d_in[19];
        ln2g = (const float*)d_in[20]; ln2b = (const float*)d_in[21];
        ln3g = (const float*)d_in[22]; ln3b = (const float*)d_in[23];
    }
    rw = (const float*)d_in[24]; rb = (const float*)d_in[25];
    w1 = (const float*)d_in[26]; b1 = (const float*)d_in[27];
    w2 = (const float*)d_in[28]; b2 = (const float*)d_in[29];

    float *wt, *q, *k, *v, *k2, *v2, *ctx, *attn, *t1, *t1t, *t2, *t2t;
    cudaGetSymbolAddress((void**)&wt,   g_wt);
    cudaGetSymbolAddress((void**)&q,    g_q);
    cudaGetSymbolAddress((void**)&k,    g_k);
    cudaGetSymbolAddress((void**)&v,    g_v);
    cudaGetSymbolAddress((void**)&k2,   g_k2);
    cudaGetSymbolAddress((void**)&v2,   g_v2);
    cudaGetSymbolAddress((void**)&ctx,  g_ctx);
    cudaGetSymbolAddress((void**)&attn, g_attn);
    cudaGetSymbolAddress((void**)&t1,   g_t1);
    cudaGetSymbolAddress((void**)&t1t,  g_t1t);
    cudaGetSymbolAddress((void**)&t2,   g_t2);
    cudaGetSymbolAddress((void**)&t2t,  g_t2t);

    const float* wt_saq = wt + 0 * PQ;
    const float* wt_sak = wt + 1 * PQ;
    const float* wt_sav = wt + 2 * PQ;
    const float* wt_sao = wt + 3 * PQ;
    const float* wt_caq = wt + 4 * PQ;
    const float* wt_cak = wt + 5 * PQ;
    const float* wt_cav = wt + 6 * PQ;
    const float* wt_cao = wt + 7 * PQ;
    const float* wt_w1  = wt + 8 * PQ;
    const float* wt_w2  = wt + 24 * PQ;
    const float* tgt_t  = wt + 40 * PQ;
    const float* mem_t  = wt + 42 * PQ;

    float* out = (float*)d_out;

    cudaFuncSetAttribute(proj_qkv_kernel,  cudaFuncAttributeMaxDynamicSharedMemorySize, GEMM_SMEM);
    cudaFuncSetAttribute(proj_qkvr_kernel, cudaFuncAttributeMaxDynamicSharedMemorySize, GEMM_SMEM);
    cudaFuncSetAttribute(proj_qkv5_kernel, cudaFuncAttributeMaxDynamicSharedMemorySize, GEMM_SMEM);
    cudaFuncSetAttribute(moe1_kernel,      cudaFuncAttributeMaxDynamicSharedMemorySize, GEMM_SMEM);
    cudaFuncSetAttribute(moe2_kernel,      cudaFuncAttributeMaxDynamicSharedMemorySize, GEMM_SMEM);
    cudaFuncSetAttribute(attn_tc_kernel,   cudaFuncAttributeMaxDynamicSharedMemorySize, ATC_SMEM);

    dim3 gQKV5(DM / BN, NTOK / BM, 5);     // (8, 16, 5)
    dim3 gQ1  (DM / BN, NTOK / BM, 1);     // (8, 16, 1)
    dim3 gAttn(TT / AQT, HH, BB);          // (16, 16, 4)
    dim3 gMoe1(FF / BN, NTOK / BM, EE);
    dim3 gMoe2(DM / BN, NTOK / BM, EE);
    dim3 gPrep(256, 12);

    prep_kernel<<<gPrep, 256>>>(sa_wq, sa_wk, sa_wv, sa_wo, ca_wq, ca_wk, ca_wv, ca_wo,
                                w1, w2, tgt, mem);

    // ---- all projections that depend only on inputs: sa QKV + ca KV ----
    proj_qkv5_kernel<<<gQKV5, 256, GEMM_SMEM>>>(
        tgt_t, tgt_t, tgt_t, mem_t, mem_t,
        wt_saq, wt_sak, wt_sav, wt_cak, wt_cav,
        sa_bq, sa_bk, sa_bv, ca_bk, ca_bv,
        q, k, v, k2, v2, DM, DM);

    // ---- self attention ----
    attn_tc_kernel<<<gAttn, 512, ATC_SMEM>>>(q, k, v, ctx);
    proj_qkv_kernel<<<gQ1, 256, GEMM_SMEM>>>(ctx, ctx, ctx, wt_sao, wt_sao, wt_sao,
                                             sa_bo, sa_bo, sa_bo, attn, attn, attn, DM, DM);
    add_ln_kernel<<<NTOK, 256>>>(attn, tgt, ln1g, ln1b, t1, t1t);

    // ---- cross attention ----
    proj_qkvr_kernel<<<gQ1, 256, GEMM_SMEM>>>(t1t, t1t, t1t, wt_caq, wt_caq, wt_caq,
                                              ca_bq, ca_bq, ca_bq, q, q, q, DM, DM);
    attn_tc_kernel<<<gAttn, 512, ATC_SMEM>>>(q, k2, v2, ctx);
    proj_qkv_kernel<<<gQ1, 256, GEMM_SMEM>>>(ctx, ctx, ctx, wt_cao, wt_cao, wt_cao,
                                             ca_bo, ca_bo, ca_bo, attn, attn, attn, DM, DM);
    add_ln_kernel<<<NTOK, 256>>>(attn, t1, ln2g, ln2b, t2, t2t);

    // ---- MoE (sparse top-2, slot-based scatter) ----
    router_kernel<<<NTOK, 256>>>(t2, rw, rb);
    moe1_kernel<<<gMoe1, 256, GEMM_SMEM>>>(t2t, wt_w1, b1);
    moe2_kernel<<<gMoe2, 256, GEMM_SMEM>>>(wt_w2, b2);
    add_ln_moe_kernel<<<NTOK, 256>>>(t2, ln3g, ln3b, out);

    if (out_size > NTOK * DM)
        lb_kernel<<<1, 1>>>(out + (size_t)NTOK * DM);
}

// round 12
// speedup vs baseline: 1.1032x; 1.1032x over previous
#include <cuda_runtime.h>
#include <cuda_bf16.h>
#include <math.h>
#include <stdint.h>

// ---------------- problem constants ----------------
#define BB   4
#define TT   512
#define DM   1024
#define HH   16
#define DH   64
#define FF   2048
#define EE   8
#define NTOK 2048
#define EPSL 1e-5f

// GEMM tiling (128x128x16 tile, 512 threads = 16 warps, 2m x 8n)
#define BM 128
#define BN 128
#define BKT 16
#define AS_STRIDE 20
#define BS_STRIDE 136
#define NSTAGE 3
#define A_ELEMS (BM * AS_STRIDE)    // 2560
#define B_ELEMS (BKT * BS_STRIDE)   // 2176
#define GEMM_SMEM (NSTAGE * (A_ELEMS + B_ELEMS) * 4)   // 56832

// pre-converted (tf32-rounded) constant pool layout, units of floats
#define PQ 1048576ull
#define WT_TOTAL (44ull * PQ)

// ---------------- static scratch ----------------
__device__ float g_wt  [WT_TOTAL];
__device__ float g_q   [NTOK * DM];
__device__ float g_k   [NTOK * DM];
__device__ float g_v   [NTOK * DM];
__device__ float g_k2  [NTOK * DM];
__device__ float g_v2  [NTOK * DM];
__device__ float g_ctx [NTOK * DM];
__device__ float g_attn[NTOK * DM];
__device__ float g_t1  [NTOK * DM];
__device__ float g_t1t [NTOK * DM];
__device__ float g_t2  [NTOK * DM];
__device__ float g_t2t [NTOK * DM];
__device__ float g_ys  [NTOK * 2 * DM];
__device__ float g_h   [(size_t)EE * NTOK * FF];
__device__ int   g_elist[EE * NTOK];
__device__ int   g_slot [EE * NTOK];
__device__ float g_egate[EE * NTOK];
__device__ int   g_ecnt [EE];
__device__ float g_imp  [EE];

// ---------------- helpers ----------------
__device__ __forceinline__ uint32_t f2tf(float f) {
    uint32_t u;
    asm("cvt.rna.tf32.f32 %0, %1;" : "=r"(u) : "f"(f));
    return u;
}
__device__ __forceinline__ float tfr(float f) { return __uint_as_float(f2tf(f)); }

__device__ __forceinline__ void mma8(float* c, const uint32_t* a, const uint32_t* b) {
    asm volatile(
        "mma.sync.aligned.m16n8k8.row.col.f32.tf32.tf32.f32 "
        "{%0,%1,%2,%3}, {%4,%5,%6,%7}, {%8,%9}, {%0,%1,%2,%3};\n"
        : "+f"(c[0]), "+f"(c[1]), "+f"(c[2]), "+f"(c[3])
        : "r"(a[0]), "r"(a[1]), "r"(a[2]), "r"(a[3]), "r"(b[0]), "r"(b[1]));
}

__device__ __forceinline__ uint32_t smem_u32(const void* p) {
    return (uint32_t)__cvta_generic_to_shared(p);
}
__device__ __forceinline__ void cp16(uint32_t dst, const void* src, bool pred) {
    int sz = pred ? 16 : 0;
    asm volatile("cp.async.cg.shared.global [%0], [%1], 16, %2;\n"
                 :: "r"(dst), "l"(src), "r"(sz) : "memory");
}
#define CP_COMMIT  asm volatile("cp.async.commit_group;\n" ::: "memory")
#define CP_WAIT1   asm volatile("cp.async.wait_group 1;\n" ::: "memory")
#define CP_WAIT0   asm volatile("cp.async.wait_group 0;\n" ::: "memory")

__device__ __forceinline__ float block_reduce_sum(float v, float* red) {
    int lane = threadIdx.x & 31, w = threadIdx.x >> 5;
    #pragma unroll
    for (int o = 16; o; o >>= 1) v += __shfl_xor_sync(0xFFFFFFFFu, v, o);
    __syncthreads();
    if (lane == 0) red[w] = v;
    __syncthreads();
    if (w == 0) {
        v = (lane < ((int)blockDim.x >> 5)) ? red[lane] : 0.0f;
        #pragma unroll
        for (int o = 16; o; o >>= 1) v += __shfl_xor_sync(0xFFFFFFFFu, v, o);
        if (lane == 0) red[0] = v;
    }
    __syncthreads();
    return red[0];
}

// ---------------- prep: tf32-round all static operands into g_wt (+ zero init) ----------------
__global__ void prep_kernel(
    const float* s0, const float* s1, const float* s2, const float* s3,
    const float* s4, const float* s5, const float* s6, const float* s7,
    const float* s8, const float* s9, const float* s10, const float* s11)
{
    if (blockIdx.x == 0 && blockIdx.y == 0 && threadIdx.x < EE) {
        g_ecnt[threadIdx.x] = 0; g_imp[threadIdx.x] = 0.0f;
    }
    int r = blockIdx.y;
    const float* src; size_t off, cnt;
    switch (r) {
        case 0:  src = s0;  off = 0;       cnt = PQ;      break;
        case 1:  src = s1;  off = PQ;      cnt = PQ;      break;
        case 2:  src = s2;  off = 2 * PQ;  cnt = PQ;      break;
        case 3:  src = s3;  off = 3 * PQ;  cnt = PQ;      break;
        case 4:  src = s4;  off = 4 * PQ;  cnt = PQ;      break;
        case 5:  src = s5;  off = 5 * PQ;  cnt = PQ;      break;
        case 6:  src = s6;  off = 6 * PQ;  cnt = PQ;      break;
        case 7:  src = s7;  off = 7 * PQ;  cnt = PQ;      break;
        case 8:  src = s8;  off = 8 * PQ;  cnt = 16 * PQ; break;
        case 9:  src = s9;  off = 24 * PQ; cnt = 16 * PQ; break;
        case 10: src = s10; off = 40 * PQ; cnt = 2 * PQ;  break;
        default: src = s11; off = 42 * PQ; cnt = 2 * PQ;  break;
    }
    const float4* sp = (const float4*)src;
    float4* dp = (float4*)(g_wt + off);
    size_t n4 = cnt >> 2;
    for (size_t i = blockIdx.x * blockDim.x + threadIdx.x; i < n4;
         i += (size_t)gridDim.x * blockDim.x) {
        float4 v = sp[i];
        v.x = tfr(v.x); v.y = tfr(v.y); v.z = tfr(v.z); v.w = tfr(v.w);
        dp[i] = v;
    }
}

// ================= tf32 MMA GEMM core (512 threads, cp.async 3-stage) =================
// Warp grid 2m x 8n; per-warp 64x16 output (acc[4][2]).
// MODE 0: plain; MODE 1: moe gather+relu+round; MODE 2: moe slot-scatter; MODE 3: rounded out
template<int MODE>
__device__ __forceinline__ void gemm_core(
    const float* __restrict__ A, const float* __restrict__ W,
    const float* __restrict__ bias, float* __restrict__ C,
    int K, int N, int row0, int col0,
    const int* atoks, const int* slots, const float* gates)
{
    extern __shared__ uint32_t smp[];
    uint32_t* As = smp;
    uint32_t* Bs = smp + NSTAGE * A_ELEMS;

    const int tid  = threadIdx.x;
    const int lane = tid & 31;
    const int wid  = tid >> 5;          // 0..15
    const int wm   = wid >> 3;          // 0..1
    const int wn   = wid & 7;           // 0..7
    const int g    = lane >> 2;         // 0..7
    const int tig  = lane & 3;          // 0..3

    // A loader: 512 threads x 4 floats = full 128x16 tile
    const int lr0 = tid >> 2;           // 0..127
    const int akq = (tid & 3) * 4;      // 0,4,8,12
    bool p0 = true;
    const float* a0p;
    if (MODE == 1) {
        int t0 = atoks[lr0];
        p0 = (t0 >= 0);
        a0p = A + (size_t)(p0 ? t0 : 0) * K + akq;
    } else {
        a0p = A + (size_t)(row0 + lr0) * K + akq;
    }

    // B loader: 512 threads x 4 floats = full 16x128 tile
    const int kr = tid >> 5;            // 0..15
    const int nq = (tid & 31) * 4;      // 0..124
    const float* bp = W + (size_t)kr * N + col0 + nq;

    uint32_t sA0 = smem_u32(As) + (lr0 * AS_STRIDE + akq) * 4;
    uint32_t sB0 = smem_u32(Bs) + (kr * BS_STRIDE + nq) * 4;

    const int nk = K / BKT;

#define ISSUE(b, kti) do {                                     \
        cp16(sA0 + (uint32_t)(b) * (A_ELEMS * 4),              \
             a0p + (size_t)(kti) * BKT, p0);                   \
        cp16(sB0 + (uint32_t)(b) * (B_ELEMS * 4),              \
             bp + (size_t)(kti) * BKT * N, true);              \
    } while (0)

    ISSUE(0, 0); CP_COMMIT;
    ISSUE(1, 1); CP_COMMIT;

    float acc[4][2][4];
    #pragma unroll
    for (int i = 0; i < 4; i++)
        #pragma unroll
        for (int j = 0; j < 2; j++)
            #pragma unroll
            for (int r = 0; r < 4; r++) acc[i][j][r] = 0.0f;

    int buf = 0;
    for (int kt = 0; kt < nk; kt++) {
        CP_WAIT1;
        __syncthreads();
        if (kt + 2 < nk) {
            int nb = buf + 2; if (nb >= NSTAGE) nb -= NSTAGE;
            ISSUE(nb, kt + 2);
        }
        CP_COMMIT;

        const uint32_t* Ab = As + buf * A_ELEMS;
        const uint32_t* Bb = Bs + buf * B_ELEMS;
        #pragma unroll
        for (int k8 = 0; k8 < 2; k8++) {
            uint32_t af[4][4], bf[2][2];
            const uint32_t* abase = Ab + (wm * 64 + g) * AS_STRIDE + k8 * 8 + tig;
            #pragma unroll
            for (int mt = 0; mt < 4; mt++) {
                const uint32_t* p = abase + mt * 16 * AS_STRIDE;
                af[mt][0] = p[0];
                af[mt][1] = p[8 * AS_STRIDE];
                af[mt][2] = p[4];
                af[mt][3] = p[8 * AS_STRIDE + 4];
            }
            const uint32_t* bbase = Bb + (k8 * 8 + tig) * BS_STRIDE + wn * 16 + g;
            #pragma unroll
            for (int nt = 0; nt < 2; nt++) {
                bf[nt][0] = bbase[nt * 8];
                bf[nt][1] = bbase[4 * BS_STRIDE + nt * 8];
            }
            #pragma unroll
            for (int mt = 0; mt < 4; mt++)
                #pragma unroll
                for (int nt = 0; nt < 2; nt++)
                    mma8(acc[mt][nt], af[mt], bf[nt]);
        }
        buf = (buf == NSTAGE - 1) ? 0 : buf + 1;
    }
#undef ISSUE

    #pragma unroll
    for (int mt = 0; mt < 4; mt++) {
        const int lr = wm * 64 + mt * 16 + g;
        #pragma unroll
        for (int nt = 0; nt < 2; nt++) {
            float* ac = acc[mt][nt];
            const int c = col0 + wn * 16 + nt * 8 + 2 * tig;
            const float bc0 = bias[c], bc1 = bias[c + 1];
            if (MODE == 0) {
                *(float2*)&C[(size_t)(row0 + lr) * N + c]     = make_float2(ac[0] + bc0, ac[1] + bc1);
                *(float2*)&C[(size_t)(row0 + lr + 8) * N + c] = make_float2(ac[2] + bc0, ac[3] + bc1);
            } else if (MODE == 3) {
                *(float2*)&C[(size_t)(row0 + lr) * N + c]     = make_float2(tfr(ac[0] + bc0), tfr(ac[1] + bc1));
                *(float2*)&C[(size_t)(row0 + lr + 8) * N + c] = make_float2(tfr(ac[2] + bc0), tfr(ac[3] + bc1));
            } else if (MODE == 1) {
                if (atoks[lr] >= 0)
                    *(float2*)&C[(size_t)(row0 + lr) * N + c] = make_float2(
                        tfr(fmaxf(ac[0] + bc0, 0.f)), tfr(fmaxf(ac[1] + bc1, 0.f)));
                if (atoks[lr + 8] >= 0)
                    *(float2*)&C[(size_t)(row0 + lr + 8) * N + c] = make_float2(
                        tfr(fmaxf(ac[2] + bc0, 0.f)), tfr(fmaxf(ac[3] + bc1, 0.f)));
            } else {
                int sid = slots[lr]; float gt = gates[lr];
                if (sid >= 0)
                    *(float2*)&C[(size_t)sid * DM + c] =
                        make_float2(gt * (ac[0] + bc0), gt * (ac[1] + bc1));
                sid = slots[lr + 8]; gt = gates[lr + 8];
                if (sid >= 0)
                    *(float2*)&C[(size_t)sid * DM + c] =
                        make_float2(gt * (ac[2] + bc0), gt * (ac[3] + bc1));
            }
        }
    }
}

// ---------------- GEMM wrappers (512 threads) ----------------
__global__ __launch_bounds__(512, 2) void proj_qkv_kernel(
    const float* A0, const float* A1, const float* A2,
    const float* W0, const float* W1, const float* W2,
    const float* b0, const float* b1, const float* b2,
    float* C0, float* C1, float* C2, int K, int N)
{
    const int z = blockIdx.z;
    const float* A = (z == 0) ? A0 : (z == 1) ? A1 : A2;
    const float* W = (z == 0) ? W0 : (z == 1) ? W1 : W2;
    const float* b = (z == 0) ? b0 : (z == 1) ? b1 : b2;
    float*       C = (z == 0) ? C0 : (z == 1) ? C1 : C2;
    gemm_core<0>(A, W, b, C, K, N, blockIdx.y * BM, blockIdx.x * BN,
                 nullptr, nullptr, nullptr);
}

__global__ __launch_bounds__(512, 2) void proj_qkvr_kernel(
    const float* A0, const float* A1, const float* A2,
    const float* W0, const float* W1, const float* W2,
    const float* b0, const float* b1, const float* b2,
    float* C0, float* C1, float* C2, int K, int N)
{
    const int z = blockIdx.z;
    const float* A = (z == 0) ? A0 : (z == 1) ? A1 : A2;
    const float* W = (z == 0) ? W0 : (z == 1) ? W1 : W2;
    const float* b = (z == 0) ? b0 : (z == 1) ? b1 : b2;
    float*       C = (z == 0) ? C0 : (z == 1) ? C1 : C2;
    gemm_core<3>(A, W, b, C, K, N, blockIdx.y * BM, blockIdx.x * BN,
                 nullptr, nullptr, nullptr);
}

// 5-way packed rounded projections (sa_q, sa_k, sa_v, ca_k, ca_v)
__global__ __launch_bounds__(512, 2) void proj_qkv5_kernel(
    const float* A0, const float* A1, const float* A2, const float* A3, const float* A4,
    const float* W0, const float* W1, const float* W2, const float* W3, const float* W4,
    const float* b0, const float* b1, const float* b2, const float* b3, const float* b4,
    float* C0, float* C1, float* C2, float* C3, float* C4, int K, int N)
{
    const int z = blockIdx.z;
    const float* A = (z == 0) ? A0 : (z == 1) ? A1 : (z == 2) ? A2 : (z == 3) ? A3 : A4;
    const float* W = (z == 0) ? W0 : (z == 1) ? W1 : (z == 2) ? W2 : (z == 3) ? W3 : W4;
    const float* b = (z == 0) ? b0 : (z == 1) ? b1 : (z == 2) ? b2 : (z == 3) ? b3 : b4;
    float*       C = (z == 0) ? C0 : (z == 1) ? C1 : (z == 2) ? C2 : (z == 3) ? C3 : C4;
    gemm_core<3>(A, W, b, C, K, N, blockIdx.y * BM, blockIdx.x * BN,
                 nullptr, nullptr, nullptr);
}

__global__ __launch_bounds__(512, 2) void moe1_kernel(
    const float* __restrict__ X, const float* __restrict__ w1,
    const float* __restrict__ b1)
{
    const int e = blockIdx.z;
    const int cnt = g_ecnt[e];
    const int row0 = blockIdx.y * BM;
    if (row0 >= cnt) return;
    __shared__ int toks[BM];
    if (threadIdx.x < BM) {
        int r = row0 + threadIdx.x;
        toks[threadIdx.x] = (r < cnt) ? g_elist[e * NTOK + r] : -1;
    }
    __syncthreads();
    gemm_core<1>(X, w1 + (size_t)e * DM * FF, b1 + e * FF,
                 g_h + (size_t)e * NTOK * FF,
                 DM, FF, row0, blockIdx.x * BN, toks, nullptr, nullptr);
}

__global__ __launch_bounds__(512, 2) void moe2_kernel(
    const float* __restrict__ w2, const float* __restrict__ b2)
{
    const int e = blockIdx.z;
    const int cnt = g_ecnt[e];
    const int row0 = blockIdx.y * BM;
    if (row0 >= cnt) return;
    __shared__ int slts[BM];
    __shared__ float gat[BM];
    if (threadIdx.x < BM) {
        int r = row0 + threadIdx.x;
        bool ok = (r < cnt);
        slts[threadIdx.x] = ok ? g_slot[e * NTOK + r] : -1;
        gat[threadIdx.x]  = ok ? g_egate[e * NTOK + r] : 0.0f;
    }
    __syncthreads();
    gemm_core<2>(g_h + (size_t)e * NTOK * FF, w2 + (size_t)e * FF * DM,
                 b2 + e * DM, g_ys,
                 FF, DM, row0, blockIdx.x * BN, nullptr, slts, gat);
}

// ---------------- tensor-core attention (512 threads, cp.async double-buffered) ----------------
#define AQT   32
#define KT2   64
#define KSTR  68
#define VSTR  72
#define KVBUF (KT2 * VSTR)                 // 4608 floats per buffer
#define SSTR  516
#define QF_ELEMS (2 * 8 * 32 * 4)          // 2048 u32
#define ATC_SMEM ((QF_ELEMS + 2 * KVBUF + AQT * SSTR) * 4)   // 111104 B

__global__ __launch_bounds__(512, 2) void attn_tc_kernel(
    const float* __restrict__ Q, const float* __restrict__ Kk,
    const float* __restrict__ V, float* __restrict__ O)
{
    extern __shared__ float am[];
    uint32_t* Qf = (uint32_t*)am;        // [2][8][32][4] fragment-major
    float* KV = am + QF_ELEMS;           // [2][KVBUF]
    float* S  = KV + 2 * KVBUF;          // [AQT][SSTR]

    const int q0  = blockIdx.x * AQT;
    const int h   = blockIdx.y;
    const int b   = blockIdx.z;
    const int tid = threadIdx.x;
    const int lane = tid & 31;
    const int wid  = tid >> 5;          // 0..15
    const int wm   = wid >> 3;          // 0..1
    const int wn   = wid & 7;           // 0..7
    const int g    = lane >> 2;         // 0..7
    const int tig  = lane & 3;          // 0..3

    const int lrow = tid >> 3;             // 0..63
    const int lc   = (tid & 7) * 8;        // 0..56
    const float* ksrc = Kk + ((size_t)(b * TT) + lrow) * DM + h * DH + lc;
    const float* vsrc = V  + ((size_t)(b * TT) + lrow) * DM + h * DH + lc;
    uint32_t kdst = smem_u32(KV) + (lrow * KSTR + lc) * 4;
    uint32_t vdst = smem_u32(KV) + (lrow * VSTR + lc) * 4;

#define ISSUE_K(bf_, kt_) do {                                         \
        const float* s_ = ksrc + (size_t)(kt_) * KT2 * DM;             \
        uint32_t d_ = kdst + (uint32_t)(bf_) * (KVBUF * 4);            \
        cp16(d_, s_, true); cp16(d_ + 16, s_ + 4, true);               \
    } while (0)
#define ISSUE_V(bf_, kt_) do {                                         \
        const float* s_ = vsrc + (size_t)(kt_) * KT2 * DM;             \
        uint32_t d_ = vdst + (uint32_t)(bf_) * (KVBUF * 4);            \
        cp16(d_, s_, true); cp16(d_ + 16, s_ + 4, true);               \
    } while (0)

    ISSUE_K(0, 0); CP_COMMIT;

    // ---- load Q into fragment-major layout ----
    for (int i = tid; i < QF_ELEMS; i += 512) {
        int r     = i & 3;
        int lane_ = (i >> 2) & 31;
        int k8    = (i >> 7) & 7;
        int wmf   = i >> 10;
        int gg = lane_ >> 2, tt = lane_ & 3;
        int row = q0 + wmf * 16 + gg + (r & 1) * 8;
        int col = k8 * 8 + tt + (r >> 1) * 4;
        float v = Q[((size_t)(b * TT + row)) * DM + h * DH + col] * 0.125f;
        Qf[i] = __float_as_uint(v);
    }

    // ---- scores ----
    int buf = 0;
    for (int kt = 0; kt < TT / KT2; kt++) {
        const bool more = (kt + 1 < TT / KT2);
        if (more) { ISSUE_K(buf ^ 1, kt + 1); CP_COMMIT; }
        if (more) { CP_WAIT1; } else { CP_WAIT0; }
        __syncthreads();

        const float* Kb = KV + buf * KVBUF;
        float c[4] = {0.f, 0.f, 0.f, 0.f};
        #pragma unroll
        for (int k8 = 0; k8 < DH / 8; k8++) {
            uint32_t af[4];
            *(uint4*)af = *(const uint4*)(Qf + ((wm * 8 + k8) * 32 + lane) * 4);
            const uint32_t* bb = (const uint32_t*)(Kb + (wn * 8 + g) * KSTR + k8 * 8 + tig);
            uint32_t bf2[2] = { bb[0], bb[4] };
            mma8(c, af, bf2);
        }
        int col = kt * KT2 + wn * 8 + 2 * tig;
        float* s0 = S + (wm * 16 + g) * SSTR + col;
        float* s1 = S + (wm * 16 + g + 8) * SSTR + col;
        s0[0] = c[0]; s0[1] = c[1];
        s1[0] = c[2]; s1[1] = c[3];
        __syncthreads();
        buf ^= 1;
    }

    ISSUE_V(0, 0); CP_COMMIT;

    // ---- softmax ----
    #pragma unroll
    for (int rr = 0; rr < 2; rr++) {
        int row = wid * 2 + rr;
        float* sr = S + row * SSTR;
        float m = -1e30f;
        for (int j = lane; j < TT; j += 32) m = fmaxf(m, sr[j]);
        #pragma unroll
        for (int o = 16; o; o >>= 1) m = fmaxf(m, __shfl_xor_sync(0xFFFFFFFFu, m, o));
        float sum = 0.0f;
        for (int j = lane; j < TT; j += 32) { float ev = __expf(sr[j] - m); sr[j] = ev; sum += ev; }
        #pragma unroll
        for (int o = 16; o; o >>= 1) sum += __shfl_xor_sync(0xFFFFFFFFu, sum, o);
        float inv = 1.0f / sum;
        for (int j = lane; j < TT; j += 32) sr[j] = tfr(sr[j] * inv);
    }

    // ---- PV ----
    float acc[4] = {0.f, 0.f, 0.f, 0.f};
    buf = 0;
    for (int vt = 0; vt < TT / KT2; vt++) {
        const bool more = (vt + 1 < TT / KT2);
        if (more) { ISSUE_V(buf ^ 1, vt + 1); CP_COMMIT; }
        if (more) { CP_WAIT1; } else { CP_WAIT0; }
        __syncthreads();

        const float* Vb = KV + buf * KVBUF;
        #pragma unroll
        for (int k8 = 0; k8 < KT2 / 8; k8++) {
            uint32_t af[4];
            const uint32_t* ab = (const uint32_t*)(S + (wm * 16 + g) * SSTR + vt * KT2 + k8 * 8 + tig);
            af[0] = ab[0]; af[1] = ab[8 * SSTR]; af[2] = ab[4]; af[3] = ab[8 * SSTR + 4];
            const uint32_t* bb = (const uint32_t*)(Vb + (k8 * 8 + tig) * VSTR + wn * 8 + g);
            uint32_t bf2[2] = { bb[0], bb[4 * VSTR] };
            mma8(acc, af, bf2);
        }
        __syncthreads();
        buf ^= 1;
    }
#undef ISSUE_K
#undef ISSUE_V

    {
        int col = h * DH + wn * 8 + 2 * tig;
        size_t r0 = (size_t)(b * TT + q0 + wm * 16 + g) * DM + col;
        size_t r1 = (size_t)(b * TT + q0 + wm * 16 + g + 8) * DM + col;
        O[r0]     = tfr(acc[0]); O[r0 + 1] = tfr(acc[1]);
        O[r1]     = tfr(acc[2]); O[r1 + 1] = tfr(acc[3]);
    }
}

// ---------------- add + layernorm (dual output) ----------------
__global__ __launch_bounds__(256) void add_ln_kernel(
    const float* __restrict__ x, const float* __restrict__ r,
    const float* __restrict__ g, const float* __restrict__ be,
    float* __restrict__ out, float* __restrict__ out_t)
{
    __shared__ float red[32];
    __shared__ float s_mean, s_rstd;
    int row = blockIdx.x, tid = threadIdx.x;
    const float* xp = x + (size_t)row * DM;
    const float* rp = r + (size_t)row * DM;
    float v[4]; float sum = 0.0f;
    #pragma unroll
    for (int i = 0; i < 4; i++) { int idx = tid + i * 256; v[i] = xp[idx] + rp[idx]; sum += v[i]; }
    sum = block_reduce_sum(sum, red);
    if (tid == 0) s_mean = sum * (1.0f / DM);
    __syncthreads();
    float mean = s_mean, vs = 0.0f;
    #pragma unroll
    for (int i = 0; i < 4; i++) { float dv = v[i] - mean; vs += dv * dv; }
    vs = block_reduce_sum(vs, red);
    if (tid == 0) s_rstd = rsqrtf(vs * (1.0f / DM) + EPSL);
    __syncthreads();
    float rs = s_rstd;
    #pragma unroll
    for (int i = 0; i < 4; i++) {
        int idx = tid + i * 256;
        float o = (v[i] - mean) * rs * g[idx] + be[idx];
        out[(size_t)row * DM + idx] = o;
        if (out_t) out_t[(size_t)row * DM + idx] = tfr(o);
    }
}

// ---------------- final add + layernorm over expert slots ----------------
__global__ __launch_bounds__(256) void add_ln_moe_kernel(
    const float* __restrict__ r, const float* __restrict__ g,
    const float* __restrict__ be, float* __restrict__ out)
{
    __shared__ float red[32];
    __shared__ float s_mean, s_rstd;
    int row = blockIdx.x, tid = threadIdx.x;
    const float* y0 = g_ys + (size_t)(row * 2) * DM;
    const float* y1 = y0 + DM;
    const float* rp = r + (size_t)row * DM;
    float v[4]; float sum = 0.0f;
    #pragma unroll
    for (int i = 0; i < 4; i++) {
        int idx = tid + i * 256;
        v[i] = y0[idx] + y1[idx] + rp[idx];
        sum += v[i];
    }
    sum = block_reduce_sum(sum, red);
    if (tid == 0) s_mean = sum * (1.0f / DM);
    __syncthreads();
    float mean = s_mean, vs = 0.0f;
    #pragma unroll
    for (int i = 0; i < 4; i++) { float dv = v[i] - mean; vs += dv * dv; }
    vs = block_reduce_sum(vs, red);
    if (tid == 0) s_rstd = rsqrtf(vs * (1.0f / DM) + EPSL);
    __syncthreads();
    float rs = s_rstd;
    #pragma unroll
    for (int i = 0; i < 4; i++) {
        int idx = tid + i * 256;
        out[(size_t)row * DM + idx] = (v[i] - mean) * rs * g[idx] + be[idx];
    }
}

// ---------------- router ----------------
__global__ __launch_bounds__(256) void router_kernel(
    const float* __restrict__ x, const float* __restrict__ rw,
    const float* __restrict__ rb)
{
    int t = blockIdx.x;
    int tid = threadIdx.x, lane = tid & 31, w = tid >> 5;
    __shared__ float logits[EE];
    const float* xp = x + (size_t)t * DM;
    float acc = 0.0f;
    for (int d = lane; d < DM; d += 32) acc += xp[d] * rw[d * EE + w];
    #pragma unroll
    for (int o = 16; o; o >>= 1) acc += __shfl_xor_sync(0xFFFFFFFFu, acc, o);
    if (lane == 0) logits[w] = acc + rb[w];
    __syncthreads();
    if (tid == 0) {
        float m = logits[0];
        #pragma unroll
        for (int e = 1; e < EE; e++) m = fmaxf(m, logits[e]);
        float p[EE], sum = 0.0f;
        #pragma unroll
        for (int e = 0; e < EE; e++) { p[e] = __expf(logits[e] - m); sum += p[e]; }
        float inv = 1.0f / sum;
        #pragma unroll
        for (int e = 0; e < EE; e++) { p[e] *= inv; atomicAdd(&g_imp[e], p[e]); }
        int i0 = 0;
        #pragma unroll
        for (int e = 1; e < EE; e++) if (p[e] > p[i0]) i0 = e;
        int i1 = (i0 == 0) ? 1 : 0;
        #pragma unroll
        for (int e = 0; e < EE; e++) if (e != i0 && p[e] > p[i1]) i1 = e;
        float g0 = p[i0], g1 = p[i1], gs = 1.0f / (g0 + g1);
        g0 *= gs; g1 *= gs;
        int pos = atomicAdd(&g_ecnt[i0], 1);
        g_elist[i0 * NTOK + pos] = t; g_egate[i0 * NTOK + pos] = g0;
        g_slot[i0 * NTOK + pos] = 2 * t;
        pos = atomicAdd(&g_ecnt[i1], 1);
        g_elist[i1 * NTOK + pos] = t; g_egate[i1 * NTOK + pos] = g1;
        g_slot[i1 * NTOK + pos] = 2 * t + 1;
    }
}

// ---------------- load-balance loss ----------------
__global__ void lb_kernel(float* __restrict__ out) {
    float lb = 0.0f;
    #pragma unroll
    for (int e = 0; e < EE; e++)
        lb += ((float)g_ecnt[e] / (float)(NTOK * 2)) * (g_imp[e] / (float)NTOK);
    out[0] = (float)EE * lb;
}

// ---------------- host launcher ----------------
extern "C" void kernel_launch(void* const* d_in, const int* in_sizes, int n_in,
                              void* d_out, int out_size)
{
    const float* tgt = (const float*)d_in[0];
    const float* mem = (const float*)d_in[1];
    const float *sa_wq, *sa_wk, *sa_wv, *sa_wo, *ca_wq, *ca_wk, *ca_wv, *ca_wo;
    const float *sa_bq, *sa_bk, *sa_bv, *sa_bo, *ca_bq, *ca_bk, *ca_bv, *ca_bo;
    const float *ln1g, *ln1b, *ln2g, *ln2b, *ln3g, *ln3b, *rw, *rb, *w1, *b1, *w2, *b2;

    if (in_sizes[5] == DM * DM) {
        sa_wq = (const float*)d_in[2];  sa_wk = (const float*)d_in[3];
        sa_wv = (const float*)d_in[4];  sa_wo = (const float*)d_in[5];
        ca_wq = (const float*)d_in[6];  ca_wk = (const float*)d_in[7];
        ca_wv = (const float*)d_in[8];  ca_wo = (const float*)d_in[9];
        sa_bq = (const float*)d_in[10]; sa_bk = (const float*)d_in[11];
        sa_bv = (const float*)d_in[12]; sa_bo = (const float*)d_in[13];
        ca_bq = (const float*)d_in[14]; ca_bk = (const float*)d_in[15];
        ca_bv = (const float*)d_in[16]; ca_bo = (const float*)d_in[17];
        ln1g = (const float*)d_in[18]; ln2g = (const float*)d_in[19]; ln3g = (const float*)d_in[20];
        ln1b = (const float*)d_in[21]; ln2b = (const float*)d_in[22]; ln3b = (const float*)d_in[23];
    } else {
        sa_wq = (const float*)d_in[2];  sa_wk = (const float*)d_in[3];
        sa_wv = (const float*)d_in[4];
        sa_bq = (const float*)d_in[5];  sa_bk = (const float*)d_in[6];
        sa_bv = (const float*)d_in[7];
        sa_wo = (const float*)d_in[8];  sa_bo = (const float*)d_in[9];
        ca_wq = (const float*)d_in[10]; ca_wk = (const float*)d_in[11];
        ca_wv = (const float*)d_in[12];
        ca_bq = (const float*)d_in[13]; ca_bk = (const float*)d_in[14];
        ca_bv = (const float*)d_in[15];
        ca_wo = (const float*)d_in[16]; ca_bo = (const float*)d_in[17];
        ln1g = (const float*)d_in[18]; ln1b = (const float*)d_in[19];
        ln2g = (const float*)d_in[20]; ln2b = (const float*)d_in[21];
        ln3g = (const float*)d_in[22]; ln3b = (const float*)d_in[23];
    }
    rw = (const float*)d_in[24]; rb = (const float*)d_in[25];
    w1 = (const float*)d_in[26]; b1 = (const float*)d_in[27];
    w2 = (const float*)d_in[28]; b2 = (const float*)d_in[29];

    float *wt, *q, *k, *v, *k2, *v2, *ctx, *attn, *t1, *t1t, *t2, *t2t;
    cudaGetSymbolAddress((void**)&wt,   g_wt);
    cudaGetSymbolAddress((void**)&q,    g_q);
    cudaGetSymbolAddress((void**)&k,    g_k);
    cudaGetSymbolAddress((void**)&v,    g_v);
    cudaGetSymbolAddress((void**)&k2,   g_k2);
    cudaGetSymbolAddress((void**)&v2,   g_v2);
    cudaGetSymbolAddress((void**)&ctx,  g_ctx);
    cudaGetSymbolAddress((void**)&attn, g_attn);
    cudaGetSymbolAddress((void**)&t1,   g_t1);
    cudaGetSymbolAddress((void**)&t1t,  g_t1t);
    cudaGetSymbolAddress((void**)&t2,   g_t2);
    cudaGetSymbolAddress((void**)&t2t,  g_t2t);

    const float* wt_saq = wt + 0 * PQ;
    const float* wt_sak = wt + 1 * PQ;
    const float* wt_sav = wt + 2 * PQ;
    const float* wt_sao = wt + 3 * PQ;
    const float* wt_caq = wt + 4 * PQ;
    const float* wt_cak = wt + 5 * PQ;
    const float* wt_cav = wt + 6 * PQ;
    const float* wt_cao = wt + 7 * PQ;
    const float* wt_w1  = wt + 8 * PQ;
    const float* wt_w2  = wt + 24 * PQ;
    const float* tgt_t  = wt + 40 * PQ;
    const float* mem_t  = wt + 42 * PQ;

    float* out = (float*)d_out;

    cudaFuncSetAttribute(proj_qkv_kernel,  cudaFuncAttributeMaxDynamicSharedMemorySize, GEMM_SMEM);
    cudaFuncSetAttribute(proj_qkvr_kernel, cudaFuncAttributeMaxDynamicSharedMemorySize, GEMM_SMEM);
    cudaFuncSetAttribute(proj_qkv5_kernel, cudaFuncAttributeMaxDynamicSharedMemorySize, GEMM_SMEM);
    cudaFuncSetAttribute(moe1_kernel,      cudaFuncAttributeMaxDynamicSharedMemorySize, GEMM_SMEM);
    cudaFuncSetAttribute(moe2_kernel,      cudaFuncAttributeMaxDynamicSharedMemorySize, GEMM_SMEM);
    cudaFuncSetAttribute(attn_tc_kernel,   cudaFuncAttributeMaxDynamicSharedMemorySize, ATC_SMEM);

    dim3 gQKV5(DM / BN, NTOK / BM, 5);     // (8, 16, 5)
    dim3 gQ1  (DM / BN, NTOK / BM, 1);     // (8, 16, 1)
    dim3 gAttn(TT / AQT, HH, BB);          // (16, 16, 4)
    dim3 gMoe1(FF / BN, NTOK / BM, EE);
    dim3 gMoe2(DM / BN, NTOK / BM, EE);
    dim3 gPrep(256, 12);

    prep_kernel<<<gPrep, 256>>>(sa_wq, sa_wk, sa_wv, sa_wo, ca_wq, ca_wk, ca_wv, ca_wo,
                                w1, w2, tgt, mem);

    // ---- all projections that depend only on inputs: sa QKV + ca KV ----
    proj_qkv5_kernel<<<gQKV5, 512, GEMM_SMEM>>>(
        tgt_t, tgt_t, tgt_t, mem_t, mem_t,
        wt_saq, wt_sak, wt_sav, wt_cak, wt_cav,
        sa_bq, sa_bk, sa_bv, ca_bk, ca_bv,
        q, k, v, k2, v2, DM, DM);

    // ---- self attention ----
    attn_tc_kernel<<<gAttn, 512, ATC_SMEM>>>(q, k, v, ctx);
    proj_qkv_kernel<<<gQ1, 512, GEMM_SMEM>>>(ctx, ctx, ctx, wt_sao, wt_sao, wt_sao,
                                             sa_bo, sa_bo, sa_bo, attn, attn, attn, DM, DM);
    add_ln_kernel<<<NTOK, 256>>>(attn, tgt, ln1g, ln1b, t1, t1t);

    // ---- cross attention ----
    proj_qkvr_kernel<<<gQ1, 512, GEMM_SMEM>>>(t1t, t1t, t1t, wt_caq, wt_caq, wt_caq,
                                              ca_bq, ca_bq, ca_bq, q, q, q, DM, DM);
    attn_tc_kernel<<<gAttn, 512, ATC_SMEM>>>(q, k2, v2, ctx);
    proj_qkv_kernel<<<gQ1, 512, GEMM_SMEM>>>(ctx, ctx, ctx, wt_cao, wt_cao, wt_cao,
                                             ca_bo, ca_bo, ca_bo, attn, attn, attn, DM, DM);
    add_ln_kernel<<<NTOK, 256>>>(attn, t1, ln2g, ln2b, t2, t2t);

    // ---- MoE (sparse top-2, slot-based scatter) ----
    router_kernel<<<NTOK, 256>>>(t2, rw, rb);
    moe1_kernel<<<gMoe1, 512, GEMM_SMEM>>>(t2t, wt_w1, b1);
    moe2_kernel<<<gMoe2, 512, GEMM_SMEM>>>(wt_w2, b2);
    add_ln_moe_kernel<<<NTOK, 256>>>(t2, ln3g, ln3b, out);

    if (out_size > NTOK * DM)
        lb_kernel<<<1, 1>>>(out + (size_t)NTOK * DM);
}

// round 13
// speedup vs baseline: 1.1461x; 1.0389x over previous
#include <cuda_runtime.h>
#include <cuda_bf16.h>
#include <math.h>
#include <stdint.h>

// ---------------- problem constants ----------------
#define BB   4
#define TT   512
#define DM   1024
#define HH   16
#define DH   64
#define FF   2048
#define EE   8
#define NTOK 2048
#define EPSL 1e-5f

// GEMM tiling (round-8 proven config)
#define BM 128
#define BN 128
#define BKT 16
#define AS_STRIDE 20
#define BS_STRIDE 136
#define NSTAGE 3
#define A_ELEMS (BM * AS_STRIDE)
#define B_ELEMS (BKT * BS_STRIDE)
#define GEMM_SMEM (NSTAGE * (A_ELEMS + B_ELEMS) * 4)   // 56832

// pre-converted (tf32-rounded) constant pool layout, units of floats
#define PQ 1048576ull
#define WT_TOTAL (44ull * PQ)

// ---------------- static scratch ----------------
__device__ float g_wt  [WT_TOTAL];
__device__ float g_q   [NTOK * DM];
__device__ float g_k   [NTOK * DM];
__device__ float g_v   [NTOK * DM];
__device__ float g_k2  [NTOK * DM];
__device__ float g_v2  [NTOK * DM];
__device__ float g_ctx [NTOK * DM];
__device__ float g_attn[NTOK * DM];
__device__ float g_t1  [NTOK * DM];
__device__ float g_t1t [NTOK * DM];
__device__ float g_t2  [NTOK * DM];
__device__ float g_t2t [NTOK * DM];
__device__ float g_ys  [NTOK * 2 * DM];
__device__ float g_h   [(size_t)EE * NTOK * FF];
__device__ int   g_elist[EE * NTOK];
__device__ int   g_slot [EE * NTOK];
__device__ float g_egate[EE * NTOK];
__device__ int   g_ecnt [EE];
__device__ float g_imp  [EE];

// ---------------- helpers ----------------
__device__ __forceinline__ uint32_t f2tf(float f) {
    uint32_t u;
    asm("cvt.rna.tf32.f32 %0, %1;" : "=r"(u) : "f"(f));
    return u;
}
__device__ __forceinline__ float tfr(float f) { return __uint_as_float(f2tf(f)); }

__device__ __forceinline__ void mma8(float* c, const uint32_t* a, const uint32_t* b) {
    asm volatile(
        "mma.sync.aligned.m16n8k8.row.col.f32.tf32.tf32.f32 "
        "{%0,%1,%2,%3}, {%4,%5,%6,%7}, {%8,%9}, {%0,%1,%2,%3};\n"
        : "+f"(c[0]), "+f"(c[1]), "+f"(c[2]), "+f"(c[3])
        : "r"(a[0]), "r"(a[1]), "r"(a[2]), "r"(a[3]), "r"(b[0]), "r"(b[1]));
}

__device__ __forceinline__ uint32_t smem_u32(const void* p) {
    return (uint32_t)__cvta_generic_to_shared(p);
}
__device__ __forceinline__ void cp16(uint32_t dst, const void* src, bool pred) {
    int sz = pred ? 16 : 0;
    asm volatile("cp.async.cg.shared.global [%0], [%1], 16, %2;\n"
                 :: "r"(dst), "l"(src), "r"(sz) : "memory");
}
#define CP_COMMIT  asm volatile("cp.async.commit_group;\n" ::: "memory")
#define CP_WAIT1   asm volatile("cp.async.wait_group 1;\n" ::: "memory")
#define CP_WAIT0   asm volatile("cp.async.wait_group 0;\n" ::: "memory")

__device__ __forceinline__ float block_reduce_sum(float v, float* red) {
    int lane = threadIdx.x & 31, w = threadIdx.x >> 5;
    #pragma unroll
    for (int o = 16; o; o >>= 1) v += __shfl_xor_sync(0xFFFFFFFFu, v, o);
    __syncthreads();
    if (lane == 0) red[w] = v;
    __syncthreads();
    if (w == 0) {
        v = (lane < ((int)blockDim.x >> 5)) ? red[lane] : 0.0f;
        #pragma unroll
        for (int o = 16; o; o >>= 1) v += __shfl_xor_sync(0xFFFFFFFFu, v, o);
        if (lane == 0) red[0] = v;
    }
    __syncthreads();
    return red[0];
}

// ---------------- prep: tf32-round proj weights + tgt/mem (+ zero init) ----------------
// w1/w2 rounding is folded into proj_qkv5 (z=5,6) to overlap with GEMM work.
__global__ void prep_kernel(
    const float* s0, const float* s1, const float* s2, const float* s3,
    const float* s4, const float* s5, const float* s6, const float* s7,
    const float* s10, const float* s11)
{
    if (blockIdx.x == 0 && blockIdx.y == 0 && threadIdx.x < EE) {
        g_ecnt[threadIdx.x] = 0; g_imp[threadIdx.x] = 0.0f;
    }
    int r = blockIdx.y;
    const float* src; size_t off, cnt;
    switch (r) {
        case 0:  src = s0;  off = 0;       cnt = PQ;     break;
        case 1:  src = s1;  off = PQ;      cnt = PQ;     break;
        case 2:  src = s2;  off = 2 * PQ;  cnt = PQ;     break;
        case 3:  src = s3;  off = 3 * PQ;  cnt = PQ;     break;
        case 4:  src = s4;  off = 4 * PQ;  cnt = PQ;     break;
        case 5:  src = s5;  off = 5 * PQ;  cnt = PQ;     break;
        case 6:  src = s6;  off = 6 * PQ;  cnt = PQ;     break;
        case 7:  src = s7;  off = 7 * PQ;  cnt = PQ;     break;
        case 8:  src = s10; off = 40 * PQ; cnt = 2 * PQ; break;
        default: src = s11; off = 42 * PQ; cnt = 2 * PQ; break;
    }
    const float4* sp = (const float4*)src;
    float4* dp = (float4*)(g_wt + off);
    size_t n4 = cnt >> 2;
    for (size_t i = blockIdx.x * blockDim.x + threadIdx.x; i < n4;
         i += (size_t)gridDim.x * blockDim.x) {
        float4 v = sp[i];
        v.x = tfr(v.x); v.y = tfr(v.y); v.z = tfr(v.z); v.w = tfr(v.w);
        dp[i] = v;
    }
}

// ================= tf32 MMA GEMM core (round-8 config) =================
// MODE 0: plain; MODE 1: moe gather+relu+round; MODE 2: moe slot-scatter; MODE 3: rounded out
template<int MODE>
__device__ __forceinline__ void gemm_core(
    const float* __restrict__ A, const float* __restrict__ W,
    const float* __restrict__ bias, float* __restrict__ C,
    int K, int N, int row0, int col0,
    const int* atoks, const int* slots, const float* gates)
{
    extern __shared__ uint32_t smp[];
    uint32_t* As = smp;
    uint32_t* Bs = smp + NSTAGE * A_ELEMS;

    const int tid  = threadIdx.x;
    const int lane = tid & 31;
    const int wid  = tid >> 5;
    const int wm   = wid >> 2;
    const int wn   = wid & 3;
    const int g    = lane >> 2;
    const int tig  = lane & 3;

    const int lr0 = tid >> 2;
    const int akq = (tid & 3) * 4;
    bool p0 = true, p1 = true;
    const float *a0p, *a1p;
    if (MODE == 1) {
        int t0 = atoks[lr0], t1 = atoks[lr0 + 64];
        p0 = (t0 >= 0); p1 = (t1 >= 0);
        a0p = A + (size_t)(p0 ? t0 : 0) * K + akq;
        a1p = A + (size_t)(p1 ? t1 : 0) * K + akq;
    } else {
        a0p = A + (size_t)(row0 + lr0) * K + akq;
        a1p = A + (size_t)(row0 + lr0 + 64) * K + akq;
    }

    const int kr = tid >> 4;
    const int nq = (tid & 15) * 8;
    const float* bp = W + (size_t)kr * N + col0 + nq;

    uint32_t sA0 = smem_u32(As) + (lr0 * AS_STRIDE + akq) * 4;
    uint32_t sA1 = sA0 + 64 * AS_STRIDE * 4;
    uint32_t sB0 = smem_u32(Bs) + (kr * BS_STRIDE + nq) * 4;

    const int nk = K / BKT;

#define ISSUE(b, kti) do {                                     \
        uint32_t ao = (uint32_t)(b) * (A_ELEMS * 4);           \
        cp16(sA0 + ao, a0p + (kti) * BKT, p0);                 \
        cp16(sA1 + ao, a1p + (kti) * BKT, p1);                 \
        const float* bs_ = bp + (size_t)(kti) * BKT * N;       \
        uint32_t bo = (uint32_t)(b) * (B_ELEMS * 4);           \
        cp16(sB0 + bo, bs_, true);                             \
        cp16(sB0 + bo + 16, bs_ + 4, true);                    \
    } while (0)

    ISSUE(0, 0); CP_COMMIT;
    ISSUE(1, 1); CP_COMMIT;

    float acc[4][4][4];
    #pragma unroll
    for (int i = 0; i < 4; i++)
        #pragma unroll
        for (int j = 0; j < 4; j++)
            #pragma unroll
            for (int r = 0; r < 4; r++) acc[i][j][r] = 0.0f;

    int buf = 0;
    for (int kt = 0; kt < nk; kt++) {
        CP_WAIT1;
        __syncthreads();
        if (kt + 2 < nk) {
            int nb = buf + 2; if (nb >= NSTAGE) nb -= NSTAGE;
            ISSUE(nb, kt + 2);
        }
        CP_COMMIT;

        const uint32_t* Ab = As + buf * A_ELEMS;
        const uint32_t* Bb = Bs + buf * B_ELEMS;
        #pragma unroll
        for (int k8 = 0; k8 < 2; k8++) {
            uint32_t af[4][4], bf[4][2];
            const uint32_t* abase = Ab + (wm * 64 + g) * AS_STRIDE + k8 * 8 + tig;
            #pragma unroll
            for (int mt = 0; mt < 4; mt++) {
                const uint32_t* p = abase + mt * 16 * AS_STRIDE;
                af[mt][0] = p[0];
                af[mt][1] = p[8 * AS_STRIDE];
                af[mt][2] = p[4];
                af[mt][3] = p[8 * AS_STRIDE + 4];
            }
            const uint32_t* bbase = Bb + (k8 * 8 + tig) * BS_STRIDE + wn * 32 + g;
            #pragma unroll
            for (int nt = 0; nt < 4; nt++) {
                bf[nt][0] = bbase[nt * 8];
                bf[nt][1] = bbase[4 * BS_STRIDE + nt * 8];
            }
            #pragma unroll
            for (int mt = 0; mt < 4; mt++)
                #pragma unroll
                for (int nt = 0; nt < 4; nt++)
                    mma8(acc[mt][nt], af[mt], bf[nt]);
        }
        buf = (buf == NSTAGE - 1) ? 0 : buf + 1;
    }
#undef ISSUE

    #pragma unroll
    for (int mt = 0; mt < 4; mt++) {
        const int lr = wm * 64 + mt * 16 + g;
        #pragma unroll
        for (int nt = 0; nt < 4; nt++) {
            float* ac = acc[mt][nt];
            const int c = col0 + wn * 32 + nt * 8 + 2 * tig;
            const float bc0 = bias[c], bc1 = bias[c + 1];
            if (MODE == 0) {
                *(float2*)&C[(size_t)(row0 + lr) * N + c]     = make_float2(ac[0] + bc0, ac[1] + bc1);
                *(float2*)&C[(size_t)(row0 + lr + 8) * N + c] = make_float2(ac[2] + bc0, ac[3] + bc1);
            } else if (MODE == 3) {
                *(float2*)&C[(size_t)(row0 + lr) * N + c]     = make_float2(tfr(ac[0] + bc0), tfr(ac[1] + bc1));
                *(float2*)&C[(size_t)(row0 + lr + 8) * N + c] = make_float2(tfr(ac[2] + bc0), tfr(ac[3] + bc1));
            } else if (MODE == 1) {
                if (atoks[lr] >= 0)
                    *(float2*)&C[(size_t)(row0 + lr) * N + c] = make_float2(
                        tfr(fmaxf(ac[0] + bc0, 0.f)), tfr(fmaxf(ac[1] + bc1, 0.f)));
                if (atoks[lr + 8] >= 0)
                    *(float2*)&C[(size_t)(row0 + lr + 8) * N + c] = make_float2(
                        tfr(fmaxf(ac[2] + bc0, 0.f)), tfr(fmaxf(ac[3] + bc1, 0.f)));
            } else {
                int sid = slots[lr]; float gt = gates[lr];
                if (sid >= 0)
                    *(float2*)&C[(size_t)sid * DM + c] =
                        make_float2(gt * (ac[0] + bc0), gt * (ac[1] + bc1));
                sid = slots[lr + 8]; gt = gates[lr + 8];
                if (sid >= 0)
                    *(float2*)&C[(size_t)sid * DM + c] =
                        make_float2(gt * (ac[2] + bc0), gt * (ac[3] + bc1));
            }
        }
    }
}

// ---------------- GEMM wrappers (256 threads, round-8 config) ----------------
__global__ __launch_bounds__(256, 2) void proj_qkv_kernel(
    const float* A0, const float* A1, const float* A2,
    const float* W0, const float* W1, const float* W2,
    const float* b0, const float* b1, const float* b2,
    float* C0, float* C1, float* C2, int K, int N)
{
    const int z = blockIdx.z;
    const float* A = (z == 0) ? A0 : (z == 1) ? A1 : A2;
    const float* W = (z == 0) ? W0 : (z == 1) ? W1 : W2;
    const float* b = (z == 0) ? b0 : (z == 1) ? b1 : b2;
    float*       C = (z == 0) ? C0 : (z == 1) ? C1 : C2;
    gemm_core<0>(A, W, b, C, K, N, blockIdx.y * BM, blockIdx.x * BN,
                 nullptr, nullptr, nullptr);
}

__global__ __launch_bounds__(256, 2) void proj_qkvr_kernel(
    const float* A0, const float* A1, const float* A2,
    const float* W0, const float* W1, const float* W2,
    const float* b0, const float* b1, const float* b2,
    float* C0, float* C1, float* C2, int K, int N)
{
    const int z = blockIdx.z;
    const float* A = (z == 0) ? A0 : (z == 1) ? A1 : A2;
    const float* W = (z == 0) ? W0 : (z == 1) ? W1 : W2;
    const float* b = (z == 0) ? b0 : (z == 1) ? b1 : b2;
    float*       C = (z == 0) ? C0 : (z == 1) ? C1 : C2;
    gemm_core<3>(A, W, b, C, K, N, blockIdx.y * BM, blockIdx.x * BN,
                 nullptr, nullptr, nullptr);
}

// 5-way packed rounded projections + overlapped w1/w2 rounding (z=5,6)
__global__ __launch_bounds__(256, 2) void proj_qkv5_kernel(
    const float* A0, const float* A1, const float* A2, const float* A3, const float* A4,
    const float* W0, const float* W1, const float* W2, const float* W3, const float* W4,
    const float* b0, const float* b1, const float* b2, const float* b3, const float* b4,
    float* C0, float* C1, float* C2, float* C3, float* C4,
    const float* w1raw, const float* w2raw, int K, int N)
{
    const int z = blockIdx.z;
    if (z >= 5) {
        // copy slice: round 16*PQ floats of w1 (z=5) or w2 (z=6) into g_wt
        const float4* sp = (const float4*)((z == 5) ? w1raw : w2raw);
        float4* dp = (float4*)(g_wt + ((z == 5) ? 8 * PQ : 24 * PQ));
        const size_t n4 = (16 * PQ) >> 2;
        const size_t cta = (size_t)blockIdx.y * gridDim.x + blockIdx.x;   // 0..127
        for (size_t i = cta * 256 + threadIdx.x; i < n4; i += (size_t)128 * 256) {
            float4 v = sp[i];
            v.x = tfr(v.x); v.y = tfr(v.y); v.z = tfr(v.z); v.w = tfr(v.w);
            dp[i] = v;
        }
        return;
    }
    const float* A = (z == 0) ? A0 : (z == 1) ? A1 : (z == 2) ? A2 : (z == 3) ? A3 : A4;
    const float* W = (z == 0) ? W0 : (z == 1) ? W1 : (z == 2) ? W2 : (z == 3) ? W3 : W4;
    const float* b = (z == 0) ? b0 : (z == 1) ? b1 : (z == 2) ? b2 : (z == 3) ? b3 : b4;
    float*       C = (z == 0) ? C0 : (z == 1) ? C1 : (z == 2) ? C2 : (z == 3) ? C3 : C4;
    gemm_core<3>(A, W, b, C, K, N, blockIdx.y * BM, blockIdx.x * BN,
                 nullptr, nullptr, nullptr);
}

__global__ __launch_bounds__(256, 2) void moe1_kernel(
    const float* __restrict__ X, const float* __restrict__ w1,
    const float* __restrict__ b1)
{
    const int e = blockIdx.z;
    const int cnt = g_ecnt[e];
    const int row0 = blockIdx.y * BM;
    if (row0 >= cnt) return;
    __shared__ int toks[BM];
    if (threadIdx.x < BM) {
        int r = row0 + threadIdx.x;
        toks[threadIdx.x] = (r < cnt) ? g_elist[e * NTOK + r] : -1;
    }
    __syncthreads();
    gemm_core<1>(X, w1 + (size_t)e * DM * FF, b1 + e * FF,
                 g_h + (size_t)e * NTOK * FF,
                 DM, FF, row0, blockIdx.x * BN, toks, nullptr, nullptr);
}

__global__ __launch_bounds__(256, 2) void moe2_kernel(
    const float* __restrict__ w2, const float* __restrict__ b2)
{
    const int e = blockIdx.z;
    const int cnt = g_ecnt[e];
    const int row0 = blockIdx.y * BM;
    if (row0 >= cnt) return;
    __shared__ int slts[BM];
    __shared__ float gat[BM];
    if (threadIdx.x < BM) {
        int r = row0 + threadIdx.x;
        bool ok = (r < cnt);
        slts[threadIdx.x] = ok ? g_slot[e * NTOK + r] : -1;
        gat[threadIdx.x]  = ok ? g_egate[e * NTOK + r] : 0.0f;
    }
    __syncthreads();
    gemm_core<2>(g_h + (size_t)e * NTOK * FF, w2 + (size_t)e * FF * DM,
                 b2 + e * DM, g_ys,
                 FF, DM, row0, blockIdx.x * BN, nullptr, slts, gat);
}

// ---------------- tensor-core attention (512 threads, cp.async double-buffered) ----------------
#define AQT   32
#define KT2   64
#define KSTR  68
#define VSTR  72
#define KVBUF (KT2 * VSTR)
#define SSTR  516
#define QF_ELEMS (2 * 8 * 32 * 4)
#define ATC_SMEM ((QF_ELEMS + 2 * KVBUF + AQT * SSTR) * 4)   // 111104 B

__global__ __launch_bounds__(512, 2) void attn_tc_kernel(
    const float* __restrict__ Q, const float* __restrict__ Kk,
    const float* __restrict__ V, float* __restrict__ O)
{
    extern __shared__ float am[];
    uint32_t* Qf = (uint32_t*)am;
    float* KV = am + QF_ELEMS;
    float* S  = KV + 2 * KVBUF;

    const int q0  = blockIdx.x * AQT;
    const int h   = blockIdx.y;
    const int b   = blockIdx.z;
    const int tid = threadIdx.x;
    const int lane = tid & 31;
    const int wid  = tid >> 5;
    const int wm   = wid >> 3;
    const int wn   = wid & 7;
    const int g    = lane >> 2;
    const int tig  = lane & 3;

    const int lrow = tid >> 3;
    const int lc   = (tid & 7) * 8;
    const float* ksrc = Kk + ((size_t)(b * TT) + lrow) * DM + h * DH + lc;
    const float* vsrc = V  + ((size_t)(b * TT) + lrow) * DM + h * DH + lc;
    uint32_t kdst = smem_u32(KV) + (lrow * KSTR + lc) * 4;
    uint32_t vdst = smem_u32(KV) + (lrow * VSTR + lc) * 4;

#define ISSUE_K(bf_, kt_) do {                                         \
        const float* s_ = ksrc + (size_t)(kt_) * KT2 * DM;             \
        uint32_t d_ = kdst + (uint32_t)(bf_) * (KVBUF * 4);            \
        cp16(d_, s_, true); cp16(d_ + 16, s_ + 4, true);               \
    } while (0)
#define ISSUE_V(bf_, kt_) do {                                         \
        const float* s_ = vsrc + (size_t)(kt_) * KT2 * DM;             \
        uint32_t d_ = vdst + (uint32_t)(bf_) * (KVBUF * 4);            \
        cp16(d_, s_, true); cp16(d_ + 16, s_ + 4, true);               \
    } while (0)

    ISSUE_K(0, 0); CP_COMMIT;

    for (int i = tid; i < QF_ELEMS; i += 512) {
        int r     = i & 3;
        int lane_ = (i >> 2) & 31;
        int k8    = (i >> 7) & 7;
        int wmf   = i >> 10;
        int gg = lane_ >> 2, tt = lane_ & 3;
        int row = q0 + wmf * 16 + gg + (r & 1) * 8;
        int col = k8 * 8 + tt + (r >> 1) * 4;
        float v = Q[((size_t)(b * TT + row)) * DM + h * DH + col] * 0.125f;
        Qf[i] = __float_as_uint(v);
    }

    int buf = 0;
    for (int kt = 0; kt < TT / KT2; kt++) {
        const bool more = (kt + 1 < TT / KT2);
        if (more) { ISSUE_K(buf ^ 1, kt + 1); CP_COMMIT; }
        if (more) { CP_WAIT1; } else { CP_WAIT0; }
        __syncthreads();

        const float* Kb = KV + buf * KVBUF;
        float c[4] = {0.f, 0.f, 0.f, 0.f};
        #pragma unroll
        for (int k8 = 0; k8 < DH / 8; k8++) {
            uint32_t af[4];
            *(uint4*)af = *(const uint4*)(Qf + ((wm * 8 + k8) * 32 + lane) * 4);
            const uint32_t* bb = (const uint32_t*)(Kb + (wn * 8 + g) * KSTR + k8 * 8 + tig);
            uint32_t bf2[2] = { bb[0], bb[4] };
            mma8(c, af, bf2);
        }
        int col = kt * KT2 + wn * 8 + 2 * tig;
        float* s0 = S + (wm * 16 + g) * SSTR + col;
        float* s1 = S + (wm * 16 + g + 8) * SSTR + col;
        s0[0] = c[0]; s0[1] = c[1];
        s1[0] = c[2]; s1[1] = c[3];
        __syncthreads();
        buf ^= 1;
    }

    ISSUE_V(0, 0); CP_COMMIT;

    #pragma unroll
    for (int rr = 0; rr < 2; rr++) {
        int row = wid * 2 + rr;
        float* sr = S + row * SSTR;
        float m = -1e30f;
        for (int j = lane; j < TT; j += 32) m = fmaxf(m, sr[j]);
        #pragma unroll
        for (int o = 16; o; o >>= 1) m = fmaxf(m, __shfl_xor_sync(0xFFFFFFFFu, m, o));
        float sum = 0.0f;
        for (int j = lane; j < TT; j += 32) { float ev = __expf(sr[j] - m); sr[j] = ev; sum += ev; }
        #pragma unroll
        for (int o = 16; o; o >>= 1) sum += __shfl_xor_sync(0xFFFFFFFFu, sum, o);
        float inv = 1.0f / sum;
        for (int j = lane; j < TT; j += 32) sr[j] = tfr(sr[j] * inv);
    }

    float acc[4] = {0.f, 0.f, 0.f, 0.f};
    buf = 0;
    for (int vt = 0; vt < TT / KT2; vt++) {
        const bool more = (vt + 1 < TT / KT2);
        if (more) { ISSUE_V(buf ^ 1, vt + 1); CP_COMMIT; }
        if (more) { CP_WAIT1; } else { CP_WAIT0; }
        __syncthreads();

        const float* Vb = KV + buf * KVBUF;
        #pragma unroll
        for (int k8 = 0; k8 < KT2 / 8; k8++) {
            uint32_t af[4];
            const uint32_t* ab = (const uint32_t*)(S + (wm * 16 + g) * SSTR + vt * KT2 + k8 * 8 + tig);
            af[0] = ab[0]; af[1] = ab[8 * SSTR]; af[2] = ab[4]; af[3] = ab[8 * SSTR + 4];
            const uint32_t* bb = (const uint32_t*)(Vb + (k8 * 8 + tig) * VSTR + wn * 8 + g);
            uint32_t bf2[2] = { bb[0], bb[4 * VSTR] };
            mma8(acc, af, bf2);
        }
        __syncthreads();
        buf ^= 1;
    }
#undef ISSUE_K
#undef ISSUE_V

    {
        int col = h * DH + wn * 8 + 2 * tig;
        size_t r0 = (size_t)(b * TT + q0 + wm * 16 + g) * DM + col;
        size_t r1 = (size_t)(b * TT + q0 + wm * 16 + g + 8) * DM + col;
        O[r0]     = tfr(acc[0]); O[r0 + 1] = tfr(acc[1]);
        O[r1]     = tfr(acc[2]); O[r1 + 1] = tfr(acc[3]);
    }
}

// ---------------- add + layernorm (dual output) ----------------
__global__ __launch_bounds__(256) void add_ln_kernel(
    const float* __restrict__ x, const float* __restrict__ r,
    const float* __restrict__ g, const float* __restrict__ be,
    float* __restrict__ out, float* __restrict__ out_t)
{
    __shared__ float red[32];
    __shared__ float s_mean, s_rstd;
    int row = blockIdx.x, tid = threadIdx.x;
    const float* xp = x + (size_t)row * DM;
    const float* rp = r + (size_t)row * DM;
    float v[4]; float sum = 0.0f;
    #pragma unroll
    for (int i = 0; i < 4; i++) { int idx = tid + i * 256; v[i] = xp[idx] + rp[idx]; sum += v[i]; }
    sum = block_reduce_sum(sum, red);
    if (tid == 0) s_mean = sum * (1.0f / DM);
    __syncthreads();
    float mean = s_mean, vs = 0.0f;
    #pragma unroll
    for (int i = 0; i < 4; i++) { float dv = v[i] - mean; vs += dv * dv; }
    vs = block_reduce_sum(vs, red);
    if (tid == 0) s_rstd = rsqrtf(vs * (1.0f / DM) + EPSL);
    __syncthreads();
    float rs = s_rstd;
    #pragma unroll
    for (int i = 0; i < 4; i++) {
        int idx = tid + i * 256;
        float o = (v[i] - mean) * rs * g[idx] + be[idx];
        out[(size_t)row * DM + idx] = o;
        if (out_t) out_t[(size_t)row * DM + idx] = tfr(o);
    }
}

// ---------------- add + layernorm + fused router (for LN2) ----------------
__global__ __launch_bounds__(256) void add_ln_router_kernel(
    const float* __restrict__ x, const float* __restrict__ r,
    const float* __restrict__ g, const float* __restrict__ be,
    float* __restrict__ out, float* __restrict__ out_t,
    const float* __restrict__ rw, const float* __restrict__ rb)
{
    __shared__ float red[32];
    __shared__ float s_mean, s_rstd;
    __shared__ float logits[EE];
    int row = blockIdx.x, tid = threadIdx.x;
    const float* xp = x + (size_t)row * DM;
    const float* rp = r + (size_t)row * DM;
    float v[4]; float sum = 0.0f;
    #pragma unroll
    for (int i = 0; i < 4; i++) { int idx = tid + i * 256; v[i] = xp[idx] + rp[idx]; sum += v[i]; }
    sum = block_reduce_sum(sum, red);
    if (tid == 0) s_mean = sum * (1.0f / DM);
    __syncthreads();
    float mean = s_mean, vs = 0.0f;
    #pragma unroll
    for (int i = 0; i < 4; i++) { float dv = v[i] - mean; vs += dv * dv; }
    vs = block_reduce_sum(vs, red);
    if (tid == 0) s_rstd = rsqrtf(vs * (1.0f / DM) + EPSL);
    __syncthreads();
    float rs = s_rstd;
    #pragma unroll
    for (int i = 0; i < 4; i++) {
        int idx = tid + i * 256;
        float o = (v[i] - mean) * rs * g[idx] + be[idx];
        out[(size_t)row * DM + idx] = o;
        out_t[(size_t)row * DM + idx] = tfr(o);
    }
    __syncthreads();   // out row visible block-wide

    // ---- router body (verbatim indexing: identical summation order) ----
    int lane = tid & 31, w = tid >> 5;
    const float* op = out + (size_t)row * DM;
    float acc = 0.0f;
    for (int d = lane; d < DM; d += 32) acc += op[d] * rw[d * EE + w];
    #pragma unroll
    for (int o = 16; o; o >>= 1) acc += __shfl_xor_sync(0xFFFFFFFFu, acc, o);
    if (lane == 0) logits[w] = acc + rb[w];
    __syncthreads();
    if (tid == 0) {
        int t = row;
        float m = logits[0];
        #pragma unroll
        for (int e = 1; e < EE; e++) m = fmaxf(m, logits[e]);
        float p[EE], sm = 0.0f;
        #pragma unroll
        for (int e = 0; e < EE; e++) { p[e] = __expf(logits[e] - m); sm += p[e]; }
        float inv = 1.0f / sm;
        #pragma unroll
        for (int e = 0; e < EE; e++) { p[e] *= inv; atomicAdd(&g_imp[e], p[e]); }
        int i0 = 0;
        #pragma unroll
        for (int e = 1; e < EE; e++) if (p[e] > p[i0]) i0 = e;
        int i1 = (i0 == 0) ? 1 : 0;
        #pragma unroll
        for (int e = 0; e < EE; e++) if (e != i0 && p[e] > p[i1]) i1 = e;
        float g0 = p[i0], g1 = p[i1], gs = 1.0f / (g0 + g1);
        g0 *= gs; g1 *= gs;
        int pos = atomicAdd(&g_ecnt[i0], 1);
        g_elist[i0 * NTOK + pos] = t; g_egate[i0 * NTOK + pos] = g0;
        g_slot[i0 * NTOK + pos] = 2 * t;
        pos = atomicAdd(&g_ecnt[i1], 1);
        g_elist[i1 * NTOK + pos] = t; g_egate[i1 * NTOK + pos] = g1;
        g_slot[i1 * NTOK + pos] = 2 * t + 1;
    }
}

// ---------------- final add + layernorm over expert slots (+ lb loss) ----------------
__global__ __launch_bounds__(256) void add_ln_moe_kernel(
    const float* __restrict__ r, const float* __restrict__ g,
    const float* __restrict__ be, float* __restrict__ out,
    float* __restrict__ out_lb)
{
    __shared__ float red[32];
    __shared__ float s_mean, s_rstd;
    int row = blockIdx.x, tid = threadIdx.x;
    const float* y0 = g_ys + (size_t)(row * 2) * DM;
    const float* y1 = y0 + DM;
    const float* rp = r + (size_t)row * DM;
    float v[4]; float sum = 0.0f;
    #pragma unroll
    for (int i = 0; i < 4; i++) {
        int idx = tid + i * 256;
        v[i] = y0[idx] + y1[idx] + rp[idx];
        sum += v[i];
    }
    sum = block_reduce_sum(sum, red);
    if (tid == 0) s_mean = sum * (1.0f / DM);
    __syncthreads();
    float mean = s_mean, vs = 0.0f;
    #pragma unroll
    for (int i = 0; i < 4; i++) { float dv = v[i] - mean; vs += dv * dv; }
    vs = block_reduce_sum(vs, red);
    if (tid == 0) s_rstd = rsqrtf(vs * (1.0f / DM) + EPSL);
    __syncthreads();
    float rs = s_rstd;
    #pragma unroll
    for (int i = 0; i < 4; i++) {
        int idx = tid + i * 256;
        out[(size_t)row * DM + idx] = (v[i] - mean) * rs * g[idx] + be[idx];
    }
    if (row == 0 && tid == 0 && out_lb) {
        float lb = 0.0f;
        #pragma unroll
        for (int e = 0; e < EE; e++)
            lb += ((float)g_ecnt[e] / (float)(NTOK * 2)) * (g_imp[e] / (float)NTOK);
        out_lb[0] = (float)EE * lb;
    }
}

// ---------------- host launcher ----------------
extern "C" void kernel_launch(void* const* d_in, const int* in_sizes, int n_in,
                              void* d_out, int out_size)
{
    const float* tgt = (const float*)d_in[0];
    const float* mem = (const float*)d_in[1];
    const float *sa_wq, *sa_wk, *sa_wv, *sa_wo, *ca_wq, *ca_wk, *ca_wv, *ca_wo;
    const float *sa_bq, *sa_bk, *sa_bv, *sa_bo, *ca_bq, *ca_bk, *ca_bv, *ca_bo;
    const float *ln1g, *ln1b, *ln2g, *ln2b, *ln3g, *ln3b, *rw, *rb, *w1, *b1, *w2, *b2;

    if (in_sizes[5] == DM * DM) {
        sa_wq = (const float*)d_in[2];  sa_wk = (const float*)d_in[3];
        sa_wv = (const float*)d_in[4];  sa_wo = (const float*)d_in[5];
        ca_wq = (const float*)d_in[6];  ca_wk = (const float*)d_in[7];
        ca_wv = (const float*)d_in[8];  ca_wo = (const float*)d_in[9];
        sa_bq = (const float*)d_in[10]; sa_bk = (const float*)d_in[11];
        sa_bv = (const float*)d_in[12]; sa_bo = (const float*)d_in[13];
        ca_bq = (const float*)d_in[14]; ca_bk = (const float*)d_in[15];
        ca_bv = (const float*)d_in[16]; ca_bo = (const float*)d_in[17];
        ln1g = (const float*)d_in[18]; ln2g = (const float*)d_in[19]; ln3g = (const float*)d_in[20];
        ln1b = (const float*)d_in[21]; ln2b = (const float*)d_in[22]; ln3b = (const float*)d_in[23];
    } else {
        sa_wq = (const float*)d_in[2];  sa_wk = (const float*)d_in[3];
        sa_wv = (const float*)d_in[4];
        sa_bq = (const float*)d_in[5];  sa_bk = (const float*)d_in[6];
        sa_bv = (const float*)d_in[7];
        sa_wo = (const float*)d_in[8];  sa_bo = (const float*)d_in[9];
        ca_wq = (const float*)d_in[10]; ca_wk = (const float*)d_in[11];
        ca_wv = (const float*)d_in[12];
        ca_bq = (const float*)d_in[13]; ca_bk = (const float*)d_in[14];
        ca_bv = (const float*)d_in[15];
        ca_wo = (const float*)d_in[16]; ca_bo = (const float*)d_in[17];
        ln1g = (const float*)d_in[18]; ln1b = (const float*)d_in[19];
        ln2g = (const float*)d_in[20]; ln2b = (const float*)d_in[21];
        ln3g = (const float*)d_in[22]; ln3b = (const float*)d_in[23];
    }
    rw = (const float*)d_in[24]; rb = (const float*)d_in[25];
    w1 = (const float*)d_in[26]; b1 = (const float*)d_in[27];
    w2 = (const float*)d_in[28]; b2 = (const float*)d_in[29];

    float *wt, *q, *k, *v, *k2, *v2, *ctx, *attn, *t1, *t1t, *t2, *t2t;
    cudaGetSymbolAddress((void**)&wt,   g_wt);
    cudaGetSymbolAddress((void**)&q,    g_q);
    cudaGetSymbolAddress((void**)&k,    g_k);
    cudaGetSymbolAddress((void**)&v,    g_v);
    cudaGetSymbolAddress((void**)&k2,   g_k2);
    cudaGetSymbolAddress((void**)&v2,   g_v2);
    cudaGetSymbolAddress((void**)&ctx,  g_ctx);
    cudaGetSymbolAddress((void**)&attn, g_attn);
    cudaGetSymbolAddress((void**)&t1,   g_t1);
    cudaGetSymbolAddress((void**)&t1t,  g_t1t);
    cudaGetSymbolAddress((void**)&t2,   g_t2);
    cudaGetSymbolAddress((void**)&t2t,  g_t2t);

    const float* wt_saq = wt + 0 * PQ;
    const float* wt_sak = wt + 1 * PQ;
    const float* wt_sav = wt + 2 * PQ;
    const float* wt_sao = wt + 3 * PQ;
    const float* wt_caq = wt + 4 * PQ;
    const float* wt_cak = wt + 5 * PQ;
    const float* wt_cav = wt + 6 * PQ;
    const float* wt_cao = wt + 7 * PQ;
    const float* wt_w1  = wt + 8 * PQ;
    const float* wt_w2  = wt + 24 * PQ;
    const float* tgt_t  = wt + 40 * PQ;
    const float* mem_t  = wt + 42 * PQ;

    float* out = (float*)d_out;

    cudaFuncSetAttribute(proj_qkv_kernel,  cudaFuncAttributeMaxDynamicSharedMemorySize, GEMM_SMEM);
    cudaFuncSetAttribute(proj_qkvr_kernel, cudaFuncAttributeMaxDynamicSharedMemorySize, GEMM_SMEM);
    cudaFuncSetAttribute(proj_qkv5_kernel, cudaFuncAttributeMaxDynamicSharedMemorySize, GEMM_SMEM);
    cudaFuncSetAttribute(moe1_kernel,      cudaFuncAttributeMaxDynamicSharedMemorySize, GEMM_SMEM);
    cudaFuncSetAttribute(moe2_kernel,      cudaFuncAttributeMaxDynamicSharedMemorySize, GEMM_SMEM);
    cudaFuncSetAttribute(attn_tc_kernel,   cudaFuncAttributeMaxDynamicSharedMemorySize, ATC_SMEM);

    dim3 gQKV5(DM / BN, NTOK / BM, 7);     // (8, 16, 7): z 0-4 GEMM, z 5-6 w1/w2 rounding
    dim3 gQ1  (DM / BN, NTOK / BM, 1);     // (8, 16, 1)
    dim3 gAttn(TT / AQT, HH, BB);          // (16, 16, 4)
    dim3 gMoe1(FF / BN, NTOK / BM, EE);
    dim3 gMoe2(DM / BN, NTOK / BM, EE);
    dim3 gPrep(256, 10);

    prep_kernel<<<gPrep, 256>>>(sa_wq, sa_wk, sa_wv, sa_wo, ca_wq, ca_wk, ca_wv, ca_wo,
                                tgt, mem);

    // ---- input-dependent projections (sa QKV + ca KV) + overlapped w1/w2 rounding ----
    proj_qkv5_kernel<<<gQKV5, 256, GEMM_SMEM>>>(
        tgt_t, tgt_t, tgt_t, mem_t, mem_t,
        wt_saq, wt_sak, wt_sav, wt_cak, wt_cav,
        sa_bq, sa_bk, sa_bv, ca_bk, ca_bv,
        q, k, v, k2, v2, w1, w2, DM, DM);

    // ---- self attention ----
    attn_tc_kernel<<<gAttn, 512, ATC_SMEM>>>(q, k, v, ctx);
    proj_qkv_kernel<<<gQ1, 256, GEMM_SMEM>>>(ctx, ctx, ctx, wt_sao, wt_sao, wt_sao,
                                             sa_bo, sa_bo, sa_bo, attn, attn, attn, DM, DM);
    add_ln_kernel<<<NTOK, 256>>>(attn, tgt, ln1g, ln1b, t1, t1t);

    // ---- cross attention ----
    proj_qkvr_kernel<<<gQ1, 256, GEMM_SMEM>>>(t1t, t1t, t1t, wt_caq, wt_caq, wt_caq,
                                              ca_bq, ca_bq, ca_bq, q, q, q, DM, DM);
    attn_tc_kernel<<<gAttn, 512, ATC_SMEM>>>(q, k2, v2, ctx);
    proj_qkv_kernel<<<gQ1, 256, GEMM_SMEM>>>(ctx, ctx, ctx, wt_cao, wt_cao, wt_cao,
                                             ca_bo, ca_bo, ca_bo, attn, attn, attn, DM, DM);
    add_ln_router_kernel<<<NTOK, 256>>>(attn, t1, ln2g, ln2b, t2, t2t, rw, rb);

    // ---- MoE (sparse top-2, slot-based scatter) ----
    moe1_kernel<<<gMoe1, 256, GEMM_SMEM>>>(t2t, wt_w1, b1);
    moe2_kernel<<<gMoe2, 256, GEMM_SMEM>>>(wt_w2, b2);
    add_ln_moe_kernel<<<NTOK, 256>>>(t2, ln3g, ln3b, out,
        (out_size > NTOK * DM) ? (out + (size_t)NTOK * DM) : nullptr);
}

// round 14
// speedup vs baseline: 1.1705x; 1.0213x over previous
#include <cuda_runtime.h>
#include <cuda_bf16.h>
#include <math.h>
#include <stdint.h>

// ---------------- problem constants ----------------
#define BB   4
#define TT   512
#define DM   1024
#define HH   16
#define DH   64
#define FF   2048
#define EE   8
#define NTOK 2048
#define EPSL 1e-5f

// GEMM tiling (round-8 proven config)
#define BM 128
#define BN 128
#define BKT 16
#define AS_STRIDE 20
#define BS_STRIDE 136
#define NSTAGE 3
#define A_ELEMS (BM * AS_STRIDE)
#define B_ELEMS (BKT * BS_STRIDE)
#define GEMM_SMEM (NSTAGE * (A_ELEMS + B_ELEMS) * 4)   // 56832

// pre-converted (tf32-rounded) constant pool layout, units of floats
#define PQ 1048576ull
#define WT_TOTAL (44ull * PQ)

// ---------------- static scratch ----------------
__device__ float g_wt  [WT_TOTAL];
__device__ float g_q   [NTOK * DM];
__device__ float g_k   [NTOK * DM];
__device__ float g_v   [NTOK * DM];
__device__ float g_k2  [NTOK * DM];
__device__ float g_v2  [NTOK * DM];
__device__ float g_ctx [NTOK * DM];
__device__ float g_attn[NTOK * DM];
__device__ float g_ps  [NTOK * DM];     // split-K partial buffer
__device__ float g_t1  [NTOK * DM];
__device__ float g_t1t [NTOK * DM];
__device__ float g_t2  [NTOK * DM];
__device__ float g_t2t [NTOK * DM];
__device__ float g_ys  [NTOK * 2 * DM];
__device__ float g_h   [(size_t)EE * NTOK * FF];
__device__ int   g_elist[EE * NTOK];
__device__ int   g_slot [EE * NTOK];
__device__ float g_egate[EE * NTOK];
__device__ int   g_ecnt [EE];
__device__ float g_imp  [EE];

// ---------------- helpers ----------------
__device__ __forceinline__ uint32_t f2tf(float f) {
    uint32_t u;
    asm("cvt.rna.tf32.f32 %0, %1;" : "=r"(u) : "f"(f));
    return u;
}
__device__ __forceinline__ float tfr(float f) { return __uint_as_float(f2tf(f)); }

__device__ __forceinline__ void mma8(float* c, const uint32_t* a, const uint32_t* b) {
    asm volatile(
        "mma.sync.aligned.m16n8k8.row.col.f32.tf32.tf32.f32 "
        "{%0,%1,%2,%3}, {%4,%5,%6,%7}, {%8,%9}, {%0,%1,%2,%3};\n"
        : "+f"(c[0]), "+f"(c[1]), "+f"(c[2]), "+f"(c[3])
        : "r"(a[0]), "r"(a[1]), "r"(a[2]), "r"(a[3]), "r"(b[0]), "r"(b[1]));
}

__device__ __forceinline__ uint32_t smem_u32(const void* p) {
    return (uint32_t)__cvta_generic_to_shared(p);
}
__device__ __forceinline__ void cp16(uint32_t dst, const void* src, bool pred) {
    int sz = pred ? 16 : 0;
    asm volatile("cp.async.cg.shared.global [%0], [%1], 16, %2;\n"
                 :: "r"(dst), "l"(src), "r"(sz) : "memory");
}
#define CP_COMMIT  asm volatile("cp.async.commit_group;\n" ::: "memory")
#define CP_WAIT1   asm volatile("cp.async.wait_group 1;\n" ::: "memory")
#define CP_WAIT0   asm volatile("cp.async.wait_group 0;\n" ::: "memory")

__device__ __forceinline__ float block_reduce_sum(float v, float* red) {
    int lane = threadIdx.x & 31, w = threadIdx.x >> 5;
    #pragma unroll
    for (int o = 16; o; o >>= 1) v += __shfl_xor_sync(0xFFFFFFFFu, v, o);
    __syncthreads();
    if (lane == 0) red[w] = v;
    __syncthreads();
    if (w == 0) {
        v = (lane < ((int)blockDim.x >> 5)) ? red[lane] : 0.0f;
        #pragma unroll
        for (int o = 16; o; o >>= 1) v += __shfl_xor_sync(0xFFFFFFFFu, v, o);
        if (lane == 0) red[0] = v;
    }
    __syncthreads();
    return red[0];
}

// ---------------- prep: tf32-round all static operands (+ zero init) ----------------
__global__ void prep_kernel(
    const float* s0, const float* s1, const float* s2, const float* s3,
    const float* s4, const float* s5, const float* s6, const float* s7,
    const float* s8, const float* s9, const float* s10, const float* s11)
{
    if (blockIdx.x == 0 && blockIdx.y == 0 && threadIdx.x < EE) {
        g_ecnt[threadIdx.x] = 0; g_imp[threadIdx.x] = 0.0f;
    }
    int r = blockIdx.y;
    const float* src; size_t off, cnt;
    switch (r) {
        case 0:  src = s0;  off = 0;       cnt = PQ;      break;
        case 1:  src = s1;  off = PQ;      cnt = PQ;      break;
        case 2:  src = s2;  off = 2 * PQ;  cnt = PQ;      break;
        case 3:  src = s3;  off = 3 * PQ;  cnt = PQ;      break;
        case 4:  src = s4;  off = 4 * PQ;  cnt = PQ;      break;
        case 5:  src = s5;  off = 5 * PQ;  cnt = PQ;      break;
        case 6:  src = s6;  off = 6 * PQ;  cnt = PQ;      break;
        case 7:  src = s7;  off = 7 * PQ;  cnt = PQ;      break;
        case 8:  src = s8;  off = 8 * PQ;  cnt = 16 * PQ; break;
        case 9:  src = s9;  off = 24 * PQ; cnt = 16 * PQ; break;
        case 10: src = s10; off = 40 * PQ; cnt = 2 * PQ;  break;
        default: src = s11; off = 42 * PQ; cnt = 2 * PQ;  break;
    }
    const float4* sp = (const float4*)src;
    float4* dp = (float4*)(g_wt + off);
    size_t n4 = cnt >> 2;
    for (size_t i = blockIdx.x * blockDim.x + threadIdx.x; i < n4;
         i += (size_t)gridDim.x * blockDim.x) {
        float4 v = sp[i];
        v.x = tfr(v.x); v.y = tfr(v.y); v.z = tfr(v.z); v.w = tfr(v.w);
        dp[i] = v;
    }
}

// ================= tf32 MMA GEMM core (round-8 config + split-K) =================
// MODE 0: plain+bias; MODE 1: moe gather+relu+round; MODE 2: moe slot-scatter;
// MODE 3: rounded out+bias; MODE 4: raw partial (no bias) for split-K
template<int MODE>
__device__ __forceinline__ void gemm_core(
    const float* __restrict__ A, const float* __restrict__ W,
    const float* __restrict__ bias, float* __restrict__ C,
    int K, int N, int row0, int col0, int koff, int Kloop,
    const int* atoks, const int* slots, const float* gates)
{
    extern __shared__ uint32_t smp[];
    uint32_t* As = smp;
    uint32_t* Bs = smp + NSTAGE * A_ELEMS;

    const int tid  = threadIdx.x;
    const int lane = tid & 31;
    const int wid  = tid >> 5;
    const int wm   = wid >> 2;
    const int wn   = wid & 3;
    const int g    = lane >> 2;
    const int tig  = lane & 3;

    const int lr0 = tid >> 2;
    const int akq = (tid & 3) * 4;
    bool p0 = true, p1 = true;
    const float *a0p, *a1p;
    if (MODE == 1) {
        int t0 = atoks[lr0], t1 = atoks[lr0 + 64];
        p0 = (t0 >= 0); p1 = (t1 >= 0);
        a0p = A + (size_t)(p0 ? t0 : 0) * K + koff + akq;
        a1p = A + (size_t)(p1 ? t1 : 0) * K + koff + akq;
    } else {
        a0p = A + (size_t)(row0 + lr0) * K + koff + akq;
        a1p = A + (size_t)(row0 + lr0 + 64) * K + koff + akq;
    }

    const int kr = tid >> 4;
    const int nq = (tid & 15) * 8;
    const float* bp = W + (size_t)(koff + kr) * N + col0 + nq;

    uint32_t sA0 = smem_u32(As) + (lr0 * AS_STRIDE + akq) * 4;
    uint32_t sA1 = sA0 + 64 * AS_STRIDE * 4;
    uint32_t sB0 = smem_u32(Bs) + (kr * BS_STRIDE + nq) * 4;

    const int nk = Kloop / BKT;

#define ISSUE(b, kti) do {                                     \
        uint32_t ao = (uint32_t)(b) * (A_ELEMS * 4);           \
        cp16(sA0 + ao, a0p + (kti) * BKT, p0);                 \
        cp16(sA1 + ao, a1p + (kti) * BKT, p1);                 \
        const float* bs_ = bp + (size_t)(kti) * BKT * N;       \
        uint32_t bo = (uint32_t)(b) * (B_ELEMS * 4);           \
        cp16(sB0 + bo, bs_, true);                             \
        cp16(sB0 + bo + 16, bs_ + 4, true);                    \
    } while (0)

    ISSUE(0, 0); CP_COMMIT;
    ISSUE(1, 1); CP_COMMIT;

    float acc[4][4][4];
    #pragma unroll
    for (int i = 0; i < 4; i++)
        #pragma unroll
        for (int j = 0; j < 4; j++)
            #pragma unroll
            for (int r = 0; r < 4; r++) acc[i][j][r] = 0.0f;

    int buf = 0;
    for (int kt = 0; kt < nk; kt++) {
        CP_WAIT1;
        __syncthreads();
        if (kt + 2 < nk) {
            int nb = buf + 2; if (nb >= NSTAGE) nb -= NSTAGE;
            ISSUE(nb, kt + 2);
        }
        CP_COMMIT;

        const uint32_t* Ab = As + buf * A_ELEMS;
        const uint32_t* Bb = Bs + buf * B_ELEMS;
        #pragma unroll
        for (int k8 = 0; k8 < 2; k8++) {
            uint32_t af[4][4], bf[4][2];
            const uint32_t* abase = Ab + (wm * 64 + g) * AS_STRIDE + k8 * 8 + tig;
            #pragma unroll
            for (int mt = 0; mt < 4; mt++) {
                const uint32_t* p = abase + mt * 16 * AS_STRIDE;
                af[mt][0] = p[0];
                af[mt][1] = p[8 * AS_STRIDE];
                af[mt][2] = p[4];
                af[mt][3] = p[8 * AS_STRIDE + 4];
            }
            const uint32_t* bbase = Bb + (k8 * 8 + tig) * BS_STRIDE + wn * 32 + g;
            #pragma unroll
            for (int nt = 0; nt < 4; nt++) {
                bf[nt][0] = bbase[nt * 8];
                bf[nt][1] = bbase[4 * BS_STRIDE + nt * 8];
            }
            #pragma unroll
            for (int mt = 0; mt < 4; mt++)
                #pragma unroll
                for (int nt = 0; nt < 4; nt++)
                    mma8(acc[mt][nt], af[mt], bf[nt]);
        }
        buf = (buf == NSTAGE - 1) ? 0 : buf + 1;
    }
#undef ISSUE

    #pragma unroll
    for (int mt = 0; mt < 4; mt++) {
        const int lr = wm * 64 + mt * 16 + g;
        #pragma unroll
        for (int nt = 0; nt < 4; nt++) {
            float* ac = acc[mt][nt];
            const int c = col0 + wn * 32 + nt * 8 + 2 * tig;
            float bc0 = 0.f, bc1 = 0.f;
            if (MODE != 4) { bc0 = bias[c]; bc1 = bias[c + 1]; }
            if (MODE == 0) {
                *(float2*)&C[(size_t)(row0 + lr) * N + c]     = make_float2(ac[0] + bc0, ac[1] + bc1);
                *(float2*)&C[(size_t)(row0 + lr + 8) * N + c] = make_float2(ac[2] + bc0, ac[3] + bc1);
            } else if (MODE == 4) {
                *(float2*)&C[(size_t)(row0 + lr) * N + c]     = make_float2(ac[0], ac[1]);
                *(float2*)&C[(size_t)(row0 + lr + 8) * N + c] = make_float2(ac[2], ac[3]);
            } else if (MODE == 3) {
                *(float2*)&C[(size_t)(row0 + lr) * N + c]     = make_float2(tfr(ac[0] + bc0), tfr(ac[1] + bc1));
                *(float2*)&C[(size_t)(row0 + lr + 8) * N + c] = make_float2(tfr(ac[2] + bc0), tfr(ac[3] + bc1));
            } else if (MODE == 1) {
                if (atoks[lr] >= 0)
                    *(float2*)&C[(size_t)(row0 + lr) * N + c] = make_float2(
                        tfr(fmaxf(ac[0] + bc0, 0.f)), tfr(fmaxf(ac[1] + bc1, 0.f)));
                if (atoks[lr + 8] >= 0)
                    *(float2*)&C[(size_t)(row0 + lr + 8) * N + c] = make_float2(
                        tfr(fmaxf(ac[2] + bc0, 0.f)), tfr(fmaxf(ac[3] + bc1, 0.f)));
            } else {
                int sid = slots[lr]; float gt = gates[lr];
                if (sid >= 0)
                    *(float2*)&C[(size_t)sid * DM + c] =
                        make_float2(gt * (ac[0] + bc0), gt * (ac[1] + bc1));
                sid = slots[lr + 8]; gt = gates[lr + 8];
                if (sid >= 0)
                    *(float2*)&C[(size_t)sid * DM + c] =
                        make_float2(gt * (ac[2] + bc0), gt * (ac[3] + bc1));
            }
        }
    }
}

// ---------------- GEMM wrappers ----------------
// split-K(2) projection: z = K-half; partials to C0/C1 (no bias)
__global__ __launch_bounds__(256, 2) void proj_splitk_kernel(
    const float* A, const float* W, float* C0, float* C1)
{
    const int z = blockIdx.z;
    float* C = (z == 0) ? C0 : C1;
    gemm_core<4>(A, W, nullptr, C, DM, DM, blockIdx.y * BM, blockIdx.x * BN,
                 z * (DM / 2), DM / 2, nullptr, nullptr, nullptr);
}

// 5-way packed rounded projections (sa_q, sa_k, sa_v, ca_k, ca_v)
__global__ __launch_bounds__(256, 2) void proj_qkv5_kernel(
    const float* A0, const float* A1, const float* A2, const float* A3, const float* A4,
    const float* W0, const float* W1, const float* W2, const float* W3, const float* W4,
    const float* b0, const float* b1, const float* b2, const float* b3, const float* b4,
    float* C0, float* C1, float* C2, float* C3, float* C4, int K, int N)
{
    const int z = blockIdx.z;
    const float* A = (z == 0) ? A0 : (z == 1) ? A1 : (z == 2) ? A2 : (z == 3) ? A3 : A4;
    const float* W = (z == 0) ? W0 : (z == 1) ? W1 : (z == 2) ? W2 : (z == 3) ? W3 : W4;
    const float* b = (z == 0) ? b0 : (z == 1) ? b1 : (z == 2) ? b2 : (z == 3) ? b3 : b4;
    float*       C = (z == 0) ? C0 : (z == 1) ? C1 : (z == 2) ? C2 : (z == 3) ? C3 : C4;
    gemm_core<3>(A, W, b, C, K, N, blockIdx.y * BM, blockIdx.x * BN,
                 0, K, nullptr, nullptr, nullptr);
}

__global__ __launch_bounds__(256, 2) void moe1_kernel(
    const float* __restrict__ X, const float* __restrict__ w1,
    const float* __restrict__ b1)
{
    const int e = blockIdx.z;
    const int cnt = g_ecnt[e];
    const int row0 = blockIdx.y * BM;
    if (row0 >= cnt) return;
    __shared__ int toks[BM];
    if (threadIdx.x < BM) {
        int r = row0 + threadIdx.x;
        toks[threadIdx.x] = (r < cnt) ? g_elist[e * NTOK + r] : -1;
    }
    __syncthreads();
    gemm_core<1>(X, w1 + (size_t)e * DM * FF, b1 + e * FF,
                 g_h + (size_t)e * NTOK * FF,
                 DM, FF, row0, blockIdx.x * BN, 0, DM, toks, nullptr, nullptr);
}

__global__ __launch_bounds__(256, 2) void moe2_kernel(
    const float* __restrict__ w2, const float* __restrict__ b2)
{
    const int e = blockIdx.z;
    const int cnt = g_ecnt[e];
    const int row0 = blockIdx.y * BM;
    if (row0 >= cnt) return;
    __shared__ int slts[BM];
    __shared__ float gat[BM];
    if (threadIdx.x < BM) {
        int r = row0 + threadIdx.x;
        bool ok = (r < cnt);
        slts[threadIdx.x] = ok ? g_slot[e * NTOK + r] : -1;
        gat[threadIdx.x]  = ok ? g_egate[e * NTOK + r] : 0.0f;
    }
    __syncthreads();
    gemm_core<2>(g_h + (size_t)e * NTOK * FF, w2 + (size_t)e * FF * DM,
                 b2 + e * DM, g_ys,
                 FF, DM, row0, blockIdx.x * BN, 0, FF, nullptr, slts, gat);
}

// ---------------- tensor-core attention (512 threads, cp.async double-buffered) ----------------
// Q1 != nullptr: Q operand = tfr((Q+Q1+qb) * 0.125)  (split-K partials + bias)
#define AQT   32
#define KT2   64
#define KSTR  68
#define VSTR  72
#define KVBUF (KT2 * VSTR)
#define SSTR  516
#define QF_ELEMS (2 * 8 * 32 * 4)
#define ATC_SMEM ((QF_ELEMS + 2 * KVBUF + AQT * SSTR) * 4)   // 111104 B

__global__ __launch_bounds__(512, 2) void attn_tc_kernel(
    const float* __restrict__ Q, const float* __restrict__ Q1,
    const float* __restrict__ qb,
    const float* __restrict__ Kk, const float* __restrict__ V,
    float* __restrict__ O)
{
    extern __shared__ float am[];
    uint32_t* Qf = (uint32_t*)am;
    float* KV = am + QF_ELEMS;
    float* S  = KV + 2 * KVBUF;

    const int q0  = blockIdx.x * AQT;
    const int h   = blockIdx.y;
    const int b   = blockIdx.z;
    const int tid = threadIdx.x;
    const int lane = tid & 31;
    const int wid  = tid >> 5;
    const int wm   = wid >> 3;
    const int wn   = wid & 7;
    const int g    = lane >> 2;
    const int tig  = lane & 3;

    const int lrow = tid >> 3;
    const int lc   = (tid & 7) * 8;
    const float* ksrc = Kk + ((size_t)(b * TT) + lrow) * DM + h * DH + lc;
    const float* vsrc = V  + ((size_t)(b * TT) + lrow) * DM + h * DH + lc;
    uint32_t kdst = smem_u32(KV) + (lrow * KSTR + lc) * 4;
    uint32_t vdst = smem_u32(KV) + (lrow * VSTR + lc) * 4;

#define ISSUE_K(bf_, kt_) do {                                         \
        const float* s_ = ksrc + (size_t)(kt_) * KT2 * DM;             \
        uint32_t d_ = kdst + (uint32_t)(bf_) * (KVBUF * 4);            \
        cp16(d_, s_, true); cp16(d_ + 16, s_ + 4, true);               \
    } while (0)
#define ISSUE_V(bf_, kt_) do {                                         \
        const float* s_ = vsrc + (size_t)(kt_) * KT2 * DM;             \
        uint32_t d_ = vdst + (uint32_t)(bf_) * (KVBUF * 4);            \
        cp16(d_, s_, true); cp16(d_ + 16, s_ + 4, true);               \
    } while (0)

    ISSUE_K(0, 0); CP_COMMIT;

    for (int i = tid; i < QF_ELEMS; i += 512) {
        int r     = i & 3;
        int lane_ = (i >> 2) & 31;
        int k8    = (i >> 7) & 7;
        int wmf   = i >> 10;
        int gg = lane_ >> 2, tt = lane_ & 3;
        int row = q0 + wmf * 16 + gg + (r & 1) * 8;
        int col = k8 * 8 + tt + (r >> 1) * 4;
        size_t idx = ((size_t)(b * TT + row)) * DM + h * DH + col;
        float v;
        if (Q1) v = tfr((Q[idx] + Q1[idx] + qb[h * DH + col]) * 0.125f);
        else    v = Q[idx] * 0.125f;
        Qf[i] = __float_as_uint(v);
    }

    int buf = 0;
    for (int kt = 0; kt < TT / KT2; kt++) {
        const bool more = (kt + 1 < TT / KT2);
        if (more) { ISSUE_K(buf ^ 1, kt + 1); CP_COMMIT; }
        if (more) { CP_WAIT1; } else { CP_WAIT0; }
        __syncthreads();

        const float* Kb = KV + buf * KVBUF;
        float c[4] = {0.f, 0.f, 0.f, 0.f};
        #pragma unroll
        for (int k8 = 0; k8 < DH / 8; k8++) {
            uint32_t af[4];
            *(uint4*)af = *(const uint4*)(Qf + ((wm * 8 + k8) * 32 + lane) * 4);
            const uint32_t* bb = (const uint32_t*)(Kb + (wn * 8 + g) * KSTR + k8 * 8 + tig);
            uint32_t bf2[2] = { bb[0], bb[4] };
            mma8(c, af, bf2);
        }
        int col = kt * KT2 + wn * 8 + 2 * tig;
        float* s0 = S + (wm * 16 + g) * SSTR + col;
        float* s1 = S + (wm * 16 + g + 8) * SSTR + col;
        s0[0] = c[0]; s0[1] = c[1];
        s1[0] = c[2]; s1[1] = c[3];
        __syncthreads();
        buf ^= 1;
    }

    ISSUE_V(0, 0); CP_COMMIT;

    #pragma unroll
    for (int rr = 0; rr < 2; rr++) {
        int row = wid * 2 + rr;
        float* sr = S + row * SSTR;
        float m = -1e30f;
        for (int j = lane; j < TT; j += 32) m = fmaxf(m, sr[j]);
        #pragma unroll
        for (int o = 16; o; o >>= 1) m = fmaxf(m, __shfl_xor_sync(0xFFFFFFFFu, m, o));
        float sum = 0.0f;
        for (int j = lane; j < TT; j += 32) { float ev = __expf(sr[j] - m); sr[j] = ev; sum += ev; }
        #pragma unroll
        for (int o = 16; o; o >>= 1) sum += __shfl_xor_sync(0xFFFFFFFFu, sum, o);
        float inv = 1.0f / sum;
        for (int j = lane; j < TT; j += 32) sr[j] = tfr(sr[j] * inv);
    }

    float acc[4] = {0.f, 0.f, 0.f, 0.f};
    buf = 0;
    for (int vt = 0; vt < TT / KT2; vt++) {
        const bool more = (vt + 1 < TT / KT2);
        if (more) { ISSUE_V(buf ^ 1, vt + 1); CP_COMMIT; }
        if (more) { CP_WAIT1; } else { CP_WAIT0; }
        __syncthreads();

        const float* Vb = KV + buf * KVBUF;
        #pragma unroll
        for (int k8 = 0; k8 < KT2 / 8; k8++) {
            uint32_t af[4];
            const uint32_t* ab = (const uint32_t*)(S + (wm * 16 + g) * SSTR + vt * KT2 + k8 * 8 + tig);
            af[0] = ab[0]; af[1] = ab[8 * SSTR]; af[2] = ab[4]; af[3] = ab[8 * SSTR + 4];
            const uint32_t* bb = (const uint32_t*)(Vb + (k8 * 8 + tig) * VSTR + wn * 8 + g);
            uint32_t bf2[2] = { bb[0], bb[4 * VSTR] };
            mma8(acc, af, bf2);
        }
        __syncthreads();
        buf ^= 1;
    }
#undef ISSUE_K
#undef ISSUE_V

    {
        int col = h * DH + wn * 8 + 2 * tig;
        size_t r0 = (size_t)(b * TT + q0 + wm * 16 + g) * DM + col;
        size_t r1 = (size_t)(b * TT + q0 + wm * 16 + g + 8) * DM + col;
        O[r0]     = tfr(acc[0]); O[r0 + 1] = tfr(acc[1]);
        O[r1]     = tfr(acc[2]); O[r1 + 1] = tfr(acc[3]);
    }
}

// ---------------- add(2 partials + bias) + layernorm (dual output) ----------------
__global__ __launch_bounds__(256) void add_ln2_kernel(
    const float* __restrict__ x0, const float* __restrict__ x1,
    const float* __restrict__ xb, const float* __restrict__ r,
    const float* __restrict__ g, const float* __restrict__ be,
    float* __restrict__ out, float* __restrict__ out_t)
{
    __shared__ float red[32];
    __shared__ float s_mean, s_rstd;
    int row = blockIdx.x, tid = threadIdx.x;
    const float* p0 = x0 + (size_t)row * DM;
    const float* p1 = x1 + (size_t)row * DM;
    const float* rp = r + (size_t)row * DM;
    float v[4]; float sum = 0.0f;
    #pragma unroll
    for (int i = 0; i < 4; i++) {
        int idx = tid + i * 256;
        v[i] = (p0[idx] + p1[idx] + xb[idx]) + rp[idx];
        sum += v[i];
    }
    sum = block_reduce_sum(sum, red);
    if (tid == 0) s_mean = sum * (1.0f / DM);
    __syncthreads();
    float mean = s_mean, vs = 0.0f;
    #pragma unroll
    for (int i = 0; i < 4; i++) { float dv = v[i] - mean; vs += dv * dv; }
    vs = block_reduce_sum(vs, red);
    if (tid == 0) s_rstd = rsqrtf(vs * (1.0f / DM) + EPSL);
    __syncthreads();
    float rs = s_rstd;
    #pragma unroll
    for (int i = 0; i < 4; i++) {
        int idx = tid + i * 256;
        float o = (v[i] - mean) * rs * g[idx] + be[idx];
        out[(size_t)row * DM + idx] = o;
        if (out_t) out_t[(size_t)row * DM + idx] = tfr(o);
    }
}

// ---------------- add(2 partials + bias) + layernorm + fused router (LN2) ----------------
__global__ __launch_bounds__(256) void add_ln2_router_kernel(
    const float* __restrict__ x0, const float* __restrict__ x1,
    const float* __restrict__ xb, const float* __restrict__ r,
    const float* __restrict__ g, const float* __restrict__ be,
    float* __restrict__ out, float* __restrict__ out_t,
    const float* __restrict__ rw, const float* __restrict__ rb)
{
    __shared__ float red[32];
    __shared__ float s_mean, s_rstd;
    __shared__ float logits[EE];
    int row = blockIdx.x, tid = threadIdx.x;
    const float* p0 = x0 + (size_t)row * DM;
    const float* p1 = x1 + (size_t)row * DM;
    const float* rp = r + (size_t)row * DM;
    float v[4]; float sum = 0.0f;
    #pragma unroll
    for (int i = 0; i < 4; i++) {
        int idx = tid + i * 256;
        v[i] = (p0[idx] + p1[idx] + xb[idx]) + rp[idx];
        sum += v[i];
    }
    sum = block_reduce_sum(sum, red);
    if (tid == 0) s_mean = sum * (1.0f / DM);
    __syncthreads();
    float mean = s_mean, vs = 0.0f;
    #pragma unroll
    for (int i = 0; i < 4; i++) { float dv = v[i] - mean; vs += dv * dv; }
    vs = block_reduce_sum(vs, red);
    if (tid == 0) s_rstd = rsqrtf(vs * (1.0f / DM) + EPSL);
    __syncthreads();
    float rs = s_rstd;
    #pragma unroll
    for (int i = 0; i < 4; i++) {
        int idx = tid + i * 256;
        float o = (v[i] - mean) * rs * g[idx] + be[idx];
        out[(size_t)row * DM + idx] = o;
        out_t[(size_t)row * DM + idx] = tfr(o);
    }
    __syncthreads();

    // ---- router body (identical summation order to original router) ----
    int lane = tid & 31, w = tid >> 5;
    const float* op = out + (size_t)row * DM;
    float acc = 0.0f;
    for (int d = lane; d < DM; d += 32) acc += op[d] * rw[d * EE + w];
    #pragma unroll
    for (int o = 16; o; o >>= 1) acc += __shfl_xor_sync(0xFFFFFFFFu, acc, o);
    if (lane == 0) logits[w] = acc + rb[w];
    __syncthreads();
    if (tid == 0) {
        int t = row;
        float m = logits[0];
        #pragma unroll
        for (int e = 1; e < EE; e++) m = fmaxf(m, logits[e]);
        float p[EE], sm = 0.0f;
        #pragma unroll
        for (int e = 0; e < EE; e++) { p[e] = __expf(logits[e] - m); sm += p[e]; }
        float inv = 1.0f / sm;
        #pragma unroll
        for (int e = 0; e < EE; e++) { p[e] *= inv; atomicAdd(&g_imp[e], p[e]); }
        int i0 = 0;
        #pragma unroll
        for (int e = 1; e < EE; e++) if (p[e] > p[i0]) i0 = e;
        int i1 = (i0 == 0) ? 1 : 0;
        #pragma unroll
        for (int e = 0; e < EE; e++) if (e != i0 && p[e] > p[i1]) i1 = e;
        float g0 = p[i0], g1 = p[i1], gs = 1.0f / (g0 + g1);
        g0 *= gs; g1 *= gs;
        int pos = atomicAdd(&g_ecnt[i0], 1);
        g_elist[i0 * NTOK + pos] = t; g_egate[i0 * NTOK + pos] = g0;
        g_slot[i0 * NTOK + pos] = 2 * t;
        pos = atomicAdd(&g_ecnt[i1], 1);
        g_elist[i1 * NTOK + pos] = t; g_egate[i1 * NTOK + pos] = g1;
        g_slot[i1 * NTOK + pos] = 2 * t + 1;
    }
}

// ---------------- final add + layernorm over expert slots (+ lb loss) ----------------
__global__ __launch_bounds__(256) void add_ln_moe_kernel(
    const float* __restrict__ r, const float* __restrict__ g,
    const float* __restrict__ be, float* __restrict__ out,
    float* __restrict__ out_lb)
{
    __shared__ float red[32];
    __shared__ float s_mean, s_rstd;
    int row = blockIdx.x, tid = threadIdx.x;
    const float* y0 = g_ys + (size_t)(row * 2) * DM;
    const float* y1 = y0 + DM;
    const float* rp = r + (size_t)row * DM;
    float v[4]; float sum = 0.0f;
    #pragma unroll
    for (int i = 0; i < 4; i++) {
        int idx = tid + i * 256;
        v[i] = y0[idx] + y1[idx] + rp[idx];
        sum += v[i];
    }
    sum = block_reduce_sum(sum, red);
    if (tid == 0) s_mean = sum * (1.0f / DM);
    __syncthreads();
    float mean = s_mean, vs = 0.0f;
    #pragma unroll
    for (int i = 0; i < 4; i++) { float dv = v[i] - mean; vs += dv * dv; }
    vs = block_reduce_sum(vs, red);
    if (tid == 0) s_rstd = rsqrtf(vs * (1.0f / DM) + EPSL);
    __syncthreads();
    float rs = s_rstd;
    #pragma unroll
    for (int i = 0; i < 4; i++) {
        int idx = tid + i * 256;
        out[(size_t)row * DM + idx] = (v[i] - mean) * rs * g[idx] + be[idx];
    }
    if (row == 0 && tid == 0 && out_lb) {
        float lb = 0.0f;
        #pragma unroll
        for (int e = 0; e < EE; e++)
            lb += ((float)g_ecnt[e] / (float)(NTOK * 2)) * (g_imp[e] / (float)NTOK);
        out_lb[0] = (float)EE * lb;
    }
}

// ---------------- host launcher ----------------
extern "C" void kernel_launch(void* const* d_in, const int* in_sizes, int n_in,
                              void* d_out, int out_size)
{
    const float* tgt = (const float*)d_in[0];
    const float* mem = (const float*)d_in[1];
    const float *sa_wq, *sa_wk, *sa_wv, *sa_wo, *ca_wq, *ca_wk, *ca_wv, *ca_wo;
    const float *sa_bq, *sa_bk, *sa_bv, *sa_bo, *ca_bq, *ca_bk, *ca_bv, *ca_bo;
    const float *ln1g, *ln1b, *ln2g, *ln2b, *ln3g, *ln3b, *rw, *rb, *w1, *b1, *w2, *b2;

    if (in_sizes[5] == DM * DM) {
        sa_wq = (const float*)d_in[2];  sa_wk = (const float*)d_in[3];
        sa_wv = (const float*)d_in[4];  sa_wo = (const float*)d_in[5];
        ca_wq = (const float*)d_in[6];  ca_wk = (const float*)d_in[7];
        ca_wv = (const float*)d_in[8];  ca_wo = (const float*)d_in[9];
        sa_bq = (const float*)d_in[10]; sa_bk = (const float*)d_in[11];
        sa_bv = (const float*)d_in[12]; sa_bo = (const float*)d_in[13];
        ca_bq = (const float*)d_in[14]; ca_bk = (const float*)d_in[15];
        ca_bv = (const float*)d_in[16]; ca_bo = (const float*)d_in[17];
        ln1g = (const float*)d_in[18]; ln2g = (const float*)d_in[19]; ln3g = (const float*)d_in[20];
        ln1b = (const float*)d_in[21]; ln2b = (const float*)d_in[22]; ln3b = (const float*)d_in[23];
    } else {
        sa_wq = (const float*)d_in[2];  sa_wk = (const float*)d_in[3];
        sa_wv = (const float*)d_in[4];
        sa_bq = (const float*)d_in[5];  sa_bk = (const float*)d_in[6];
        sa_bv = (const float*)d_in[7];
        sa_wo = (const float*)d_in[8];  sa_bo = (const float*)d_in[9];
        ca_wq = (const float*)d_in[10]; ca_wk = (const float*)d_in[11];
        ca_wv = (const float*)d_in[12];
        ca_bq = (const float*)d_in[13]; ca_bk = (const float*)d_in[14];
        ca_bv = (const float*)d_in[15];
        ca_wo = (const float*)d_in[16]; ca_bo = (const float*)d_in[17];
        ln1g = (const float*)d_in[18]; ln1b = (const float*)d_in[19];
        ln2g = (const float*)d_in[20]; ln2b = (const float*)d_in[21];
        ln3g = (const float*)d_in[22]; ln3b = (const float*)d_in[23];
    }
    rw = (const float*)d_in[24]; rb = (const float*)d_in[25];
    w1 = (const float*)d_in[26]; b1 = (const float*)d_in[27];
    w2 = (const float*)d_in[28]; b2 = (const float*)d_in[29];

    float *wt, *q, *k, *v, *k2, *v2, *ctx, *attn, *ps, *t1, *t1t, *t2, *t2t;
    cudaGetSymbolAddress((void**)&wt,   g_wt);
    cudaGetSymbolAddress((void**)&q,    g_q);
    cudaGetSymbolAddress((void**)&k,    g_k);
    cudaGetSymbolAddress((void**)&v,    g_v);
    cudaGetSymbolAddress((void**)&k2,   g_k2);
    cudaGetSymbolAddress((void**)&v2,   g_v2);
    cudaGetSymbolAddress((void**)&ctx,  g_ctx);
    cudaGetSymbolAddress((void**)&attn, g_attn);
    cudaGetSymbolAddress((void**)&ps,   g_ps);
    cudaGetSymbolAddress((void**)&t1,   g_t1);
    cudaGetSymbolAddress((void**)&t1t,  g_t1t);
    cudaGetSymbolAddress((void**)&t2,   g_t2);
    cudaGetSymbolAddress((void**)&t2t,  g_t2t);

    const float* wt_saq = wt + 0 * PQ;
    const float* wt_sak = wt + 1 * PQ;
    const float* wt_sav = wt + 2 * PQ;
    const float* wt_sao = wt + 3 * PQ;
    const float* wt_caq = wt + 4 * PQ;
    const float* wt_cak = wt + 5 * PQ;
    const float* wt_cav = wt + 6 * PQ;
    const float* wt_cao = wt + 7 * PQ;
    const float* wt_w1  = wt + 8 * PQ;
    const float* wt_w2  = wt + 24 * PQ;
    const float* tgt_t  = wt + 40 * PQ;
    const float* mem_t  = wt + 42 * PQ;

    float* out = (float*)d_out;

    cudaFuncSetAttribute(proj_splitk_kernel, cudaFuncAttributeMaxDynamicSharedMemorySize, GEMM_SMEM);
    cudaFuncSetAttribute(proj_qkv5_kernel,   cudaFuncAttributeMaxDynamicSharedMemorySize, GEMM_SMEM);
    cudaFuncSetAttribute(moe1_kernel,        cudaFuncAttributeMaxDynamicSharedMemorySize, GEMM_SMEM);
    cudaFuncSetAttribute(moe2_kernel,        cudaFuncAttributeMaxDynamicSharedMemorySize, GEMM_SMEM);
    cudaFuncSetAttribute(attn_tc_kernel,     cudaFuncAttributeMaxDynamicSharedMemorySize, ATC_SMEM);

    dim3 gQKV5(DM / BN, NTOK / BM, 5);     // (8, 16, 5)
    dim3 gSK  (DM / BN, NTOK / BM, 2);     // (8, 16, 2): split-K halves
    dim3 gAttn(TT / AQT, HH, BB);          // (16, 16, 4)
    dim3 gMoe1(FF / BN, NTOK / BM, EE);
    dim3 gMoe2(DM / BN, NTOK / BM, EE);
    dim3 gPrep(256, 12);

    prep_kernel<<<gPrep, 256>>>(sa_wq, sa_wk, sa_wv, sa_wo, ca_wq, ca_wk, ca_wv, ca_wo,
                                w1, w2, tgt, mem);

    // ---- input-dependent projections (sa QKV + ca KV) ----
    proj_qkv5_kernel<<<gQKV5, 256, GEMM_SMEM>>>(
        tgt_t, tgt_t, tgt_t, mem_t, mem_t,
        wt_saq, wt_sak, wt_sav, wt_cak, wt_cav,
        sa_bq, sa_bk, sa_bv, ca_bk, ca_bv,
        q, k, v, k2, v2, DM, DM);

    // ---- self attention ----
    attn_tc_kernel<<<gAttn, 512, ATC_SMEM>>>(q, nullptr, nullptr, k, v, ctx);
    proj_splitk_kernel<<<gSK, 256, GEMM_SMEM>>>(ctx, wt_sao, attn, ps);
    add_ln2_kernel<<<NTOK, 256>>>(attn, ps, sa_bo, tgt, ln1g, ln1b, t1, t1t);

    // ---- cross attention ----
    proj_splitk_kernel<<<gSK, 256, GEMM_SMEM>>>(t1t, wt_caq, q, ps);
    attn_tc_kernel<<<gAttn, 512, ATC_SMEM>>>(q, ps, ca_bq, k2, v2, ctx);
    proj_splitk_kernel<<<gSK, 256, GEMM_SMEM>>>(ctx, wt_cao, attn, ps);
    add_ln2_router_kernel<<<NTOK, 256>>>(attn, ps, ca_bo, t1, ln2g, ln2b, t2, t2t, rw, rb);

    // ---- MoE (sparse top-2, slot-based scatter) ----
    moe1_kernel<<<gMoe1, 256, GEMM_SMEM>>>(t2t, wt_w1, b1);
    moe2_kernel<<<gMoe2, 256, GEMM_SMEM>>>(wt_w2, b2);
    add_ln_moe_kernel<<<NTOK, 256>>>(t2, ln3g, ln3b, out,
        (out_size > NTOK * DM) ? (out + (size_t)NTOK * DM) : nullptr);
}

// round 15
// speedup vs baseline: 1.2569x; 1.0738x over previous
#include <cuda_runtime.h>
#include <cuda_bf16.h>
#include <math.h>
#include <stdint.h>

// ---------------- problem constants ----------------
#define BB   4
#define TT   512
#define DM   1024
#define HH   16
#define DH   64
#define FF   2048
#define EE   8
#define NTOK 2048
#define EPSL 1e-5f

// GEMM tiling (round-8 proven config)
#define BM 128
#define BN 128
#define BKT 16
#define AS_STRIDE 20
#define BS_STRIDE 136
#define NSTAGE 3
#define A_ELEMS (BM * AS_STRIDE)
#define B_ELEMS (BKT * BS_STRIDE)
#define GEMM_SMEM (NSTAGE * (A_ELEMS + B_ELEMS) * 4)   // 56832

// ---------------- static scratch ----------------
__device__ float g_q   [NTOK * DM];
__device__ float g_k   [NTOK * DM];
__device__ float g_v   [NTOK * DM];
__device__ float g_k2  [NTOK * DM];
__device__ float g_v2  [NTOK * DM];
__device__ float g_ctx [NTOK * DM];
__device__ float g_attn[NTOK * DM];
__device__ float g_ps  [NTOK * DM];     // split-K partial buffer
__device__ float g_t1  [NTOK * DM];
__device__ float g_t2  [NTOK * DM];
__device__ float g_ys  [NTOK * 2 * DM];
__device__ float g_h   [(size_t)EE * NTOK * FF];
__device__ int   g_elist[EE * NTOK];
__device__ int   g_slot [EE * NTOK];
__device__ float g_egate[EE * NTOK];
__device__ int   g_ecnt [EE];
__device__ float g_imp  [EE];

// ---------------- helpers ----------------
__device__ __forceinline__ void mma8(float* c, const uint32_t* a, const uint32_t* b) {
    asm volatile(
        "mma.sync.aligned.m16n8k8.row.col.f32.tf32.tf32.f32 "
        "{%0,%1,%2,%3}, {%4,%5,%6,%7}, {%8,%9}, {%0,%1,%2,%3};\n"
        : "+f"(c[0]), "+f"(c[1]), "+f"(c[2]), "+f"(c[3])
        : "r"(a[0]), "r"(a[1]), "r"(a[2]), "r"(a[3]), "r"(b[0]), "r"(b[1]));
}

__device__ __forceinline__ uint32_t smem_u32(const void* p) {
    return (uint32_t)__cvta_generic_to_shared(p);
}
__device__ __forceinline__ void cp16(uint32_t dst, const void* src, bool pred) {
    int sz = pred ? 16 : 0;
    asm volatile("cp.async.cg.shared.global [%0], [%1], 16, %2;\n"
                 :: "r"(dst), "l"(src), "r"(sz) : "memory");
}
#define CP_COMMIT  asm volatile("cp.async.commit_group;\n" ::: "memory")
#define CP_WAIT1   asm volatile("cp.async.wait_group 1;\n" ::: "memory")
#define CP_WAIT0   asm volatile("cp.async.wait_group 0;\n" ::: "memory")

__device__ __forceinline__ float block_reduce_sum(float v, float* red) {
    int lane = threadIdx.x & 31, w = threadIdx.x >> 5;
    #pragma unroll
    for (int o = 16; o; o >>= 1) v += __shfl_xor_sync(0xFFFFFFFFu, v, o);
    __syncthreads();
    if (lane == 0) red[w] = v;
    __syncthreads();
    if (w == 0) {
        v = (lane < ((int)blockDim.x >> 5)) ? red[lane] : 0.0f;
        #pragma unroll
        for (int o = 16; o; o >>= 1) v += __shfl_xor_sync(0xFFFFFFFFu, v, o);
        if (lane == 0) red[0] = v;
    }
    __syncthreads();
    return red[0];
}

// ---------------- tiny zero ----------------
__global__ void zero_small_kernel() {
    int i = threadIdx.x;
    if (i < EE) { g_ecnt[i] = 0; g_imp[i] = 0.0f; }
}

// ================= tf32 MMA GEMM core (raw fp32 operands; HW truncates) =================
// MODE 0: plain+bias; MODE 1: moe gather+relu; MODE 2: moe slot-scatter; MODE 4: raw partial
template<int MODE>
__device__ __forceinline__ void gemm_core(
    const float* __restrict__ A, const float* __restrict__ W,
    const float* __restrict__ bias, float* __restrict__ C,
    int K, int N, int row0, int col0, int koff, int Kloop,
    const int* atoks, const int* slots, const float* gates)
{
    extern __shared__ uint32_t smp[];
    uint32_t* As = smp;
    uint32_t* Bs = smp + NSTAGE * A_ELEMS;

    const int tid  = threadIdx.x;
    const int lane = tid & 31;
    const int wid  = tid >> 5;
    const int wm   = wid >> 2;
    const int wn   = wid & 3;
    const int g    = lane >> 2;
    const int tig  = lane & 3;

    const int lr0 = tid >> 2;
    const int akq = (tid & 3) * 4;
    bool p0 = true, p1 = true;
    const float *a0p, *a1p;
    if (MODE == 1) {
        int t0 = atoks[lr0], t1 = atoks[lr0 + 64];
        p0 = (t0 >= 0); p1 = (t1 >= 0);
        a0p = A + (size_t)(p0 ? t0 : 0) * K + koff + akq;
        a1p = A + (size_t)(p1 ? t1 : 0) * K + koff + akq;
    } else {
        a0p = A + (size_t)(row0 + lr0) * K + koff + akq;
        a1p = A + (size_t)(row0 + lr0 + 64) * K + koff + akq;
    }

    const int kr = tid >> 4;
    const int nq = (tid & 15) * 8;
    const float* bp = W + (size_t)(koff + kr) * N + col0 + nq;

    uint32_t sA0 = smem_u32(As) + (lr0 * AS_STRIDE + akq) * 4;
    uint32_t sA1 = sA0 + 64 * AS_STRIDE * 4;
    uint32_t sB0 = smem_u32(Bs) + (kr * BS_STRIDE + nq) * 4;

    const int nk = Kloop / BKT;

#define ISSUE(b, kti) do {                                     \
        uint32_t ao = (uint32_t)(b) * (A_ELEMS * 4);           \
        cp16(sA0 + ao, a0p + (kti) * BKT, p0);                 \
        cp16(sA1 + ao, a1p + (kti) * BKT, p1);                 \
        const float* bs_ = bp + (size_t)(kti) * BKT * N;       \
        uint32_t bo = (uint32_t)(b) * (B_ELEMS * 4);           \
        cp16(sB0 + bo, bs_, true);                             \
        cp16(sB0 + bo + 16, bs_ + 4, true);                    \
    } while (0)

    ISSUE(0, 0); CP_COMMIT;
    ISSUE(1, 1); CP_COMMIT;

    float acc[4][4][4];
    #pragma unroll
    for (int i = 0; i < 4; i++)
        #pragma unroll
        for (int j = 0; j < 4; j++)
            #pragma unroll
            for (int r = 0; r < 4; r++) acc[i][j][r] = 0.0f;

    int buf = 0;
    for (int kt = 0; kt < nk; kt++) {
        CP_WAIT1;
        __syncthreads();
        if (kt + 2 < nk) {
            int nb = buf + 2; if (nb >= NSTAGE) nb -= NSTAGE;
            ISSUE(nb, kt + 2);
        }
        CP_COMMIT;

        const uint32_t* Ab = As + buf * A_ELEMS;
        const uint32_t* Bb = Bs + buf * B_ELEMS;
        #pragma unroll
        for (int k8 = 0; k8 < 2; k8++) {
            uint32_t af[4][4], bf[4][2];
            const uint32_t* abase = Ab + (wm * 64 + g) * AS_STRIDE + k8 * 8 + tig;
            #pragma unroll
            for (int mt = 0; mt < 4; mt++) {
                const uint32_t* p = abase + mt * 16 * AS_STRIDE;
                af[mt][0] = p[0];
                af[mt][1] = p[8 * AS_STRIDE];
                af[mt][2] = p[4];
                af[mt][3] = p[8 * AS_STRIDE + 4];
            }
            const uint32_t* bbase = Bb + (k8 * 8 + tig) * BS_STRIDE + wn * 32 + g;
            #pragma unroll
            for (int nt = 0; nt < 4; nt++) {
                bf[nt][0] = bbase[nt * 8];
                bf[nt][1] = bbase[4 * BS_STRIDE + nt * 8];
            }
            #pragma unroll
            for (int mt = 0; mt < 4; mt++)
                #pragma unroll
                for (int nt = 0; nt < 4; nt++)
                    mma8(acc[mt][nt], af[mt], bf[nt]);
        }
        buf = (buf == NSTAGE - 1) ? 0 : buf + 1;
    }
#undef ISSUE

    #pragma unroll
    for (int mt = 0; mt < 4; mt++) {
        const int lr = wm * 64 + mt * 16 + g;
        #pragma unroll
        for (int nt = 0; nt < 4; nt++) {
            float* ac = acc[mt][nt];
            const int c = col0 + wn * 32 + nt * 8 + 2 * tig;
            float bc0 = 0.f, bc1 = 0.f;
            if (MODE != 4) { bc0 = bias[c]; bc1 = bias[c + 1]; }
            if (MODE == 0) {
                *(float2*)&C[(size_t)(row0 + lr) * N + c]     = make_float2(ac[0] + bc0, ac[1] + bc1);
                *(float2*)&C[(size_t)(row0 + lr + 8) * N + c] = make_float2(ac[2] + bc0, ac[3] + bc1);
            } else if (MODE == 4) {
                *(float2*)&C[(size_t)(row0 + lr) * N + c]     = make_float2(ac[0], ac[1]);
                *(float2*)&C[(size_t)(row0 + lr + 8) * N + c] = make_float2(ac[2], ac[3]);
            } else if (MODE == 1) {
                if (atoks[lr] >= 0)
                    *(float2*)&C[(size_t)(row0 + lr) * N + c] = make_float2(
                        fmaxf(ac[0] + bc0, 0.f), fmaxf(ac[1] + bc1, 0.f));
                if (atoks[lr + 8] >= 0)
                    *(float2*)&C[(size_t)(row0 + lr + 8) * N + c] = make_float2(
                        fmaxf(ac[2] + bc0, 0.f), fmaxf(ac[3] + bc1, 0.f));
            } else {
                int sid = slots[lr]; float gt = gates[lr];
                if (sid >= 0)
                    *(float2*)&C[(size_t)sid * DM + c] =
                        make_float2(gt * (ac[0] + bc0), gt * (ac[1] + bc1));
                sid = slots[lr + 8]; gt = gates[lr + 8];
                if (sid >= 0)
                    *(float2*)&C[(size_t)sid * DM + c] =
                        make_float2(gt * (ac[2] + bc0), gt * (ac[3] + bc1));
            }
        }
    }
}

// ---------------- GEMM wrappers ----------------
// split-K(2) projection: z = K-half; partials to C0/C1 (no bias)
__global__ __launch_bounds__(256, 2) void proj_splitk_kernel(
    const float* A, const float* W, float* C0, float* C1)
{
    const int z = blockIdx.z;
    float* C = (z == 0) ? C0 : C1;
    gemm_core<4>(A, W, nullptr, C, DM, DM, blockIdx.y * BM, blockIdx.x * BN,
                 z * (DM / 2), DM / 2, nullptr, nullptr, nullptr);
}

// 5-way packed projections (sa_q, sa_k, sa_v, ca_k, ca_v)
__global__ __launch_bounds__(256, 2) void proj_qkv5_kernel(
    const float* A0, const float* A1, const float* A2, const float* A3, const float* A4,
    const float* W0, const float* W1, const float* W2, const float* W3, const float* W4,
    const float* b0, const float* b1, const float* b2, const float* b3, const float* b4,
    float* C0, float* C1, float* C2, float* C3, float* C4, int K, int N)
{
    const int z = blockIdx.z;
    const float* A = (z == 0) ? A0 : (z == 1) ? A1 : (z == 2) ? A2 : (z == 3) ? A3 : A4;
    const float* W = (z == 0) ? W0 : (z == 1) ? W1 : (z == 2) ? W2 : (z == 3) ? W3 : W4;
    const float* b = (z == 0) ? b0 : (z == 1) ? b1 : (z == 2) ? b2 : (z == 3) ? b3 : b4;
    float*       C = (z == 0) ? C0 : (z == 1) ? C1 : (z == 2) ? C2 : (z == 3) ? C3 : C4;
    gemm_core<0>(A, W, b, C, K, N, blockIdx.y * BM, blockIdx.x * BN,
                 0, K, nullptr, nullptr, nullptr);
}

__global__ __launch_bounds__(256, 2) void moe1_kernel(
    const float* __restrict__ X, const float* __restrict__ w1,
    const float* __restrict__ b1)
{
    const int e = blockIdx.z;
    const int cnt = g_ecnt[e];
    const int row0 = blockIdx.y * BM;
    if (row0 >= cnt) return;
    __shared__ int toks[BM];
    if (threadIdx.x < BM) {
        int r = row0 + threadIdx.x;
        toks[threadIdx.x] = (r < cnt) ? g_elist[e * NTOK + r] : -1;
    }
    __syncthreads();
    gemm_core<1>(X, w1 + (size_t)e * DM * FF, b1 + e * FF,
                 g_h + (size_t)e * NTOK * FF,
                 DM, FF, row0, blockIdx.x * BN, 0, DM, toks, nullptr, nullptr);
}

__global__ __launch_bounds__(256, 2) void moe2_kernel(
    const float* __restrict__ w2, const float* __restrict__ b2)
{
    const int e = blockIdx.z;
    const int cnt = g_ecnt[e];
    const int row0 = blockIdx.y * BM;
    if (row0 >= cnt) return;
    __shared__ int slts[BM];
    __shared__ float gat[BM];
    if (threadIdx.x < BM) {
        int r = row0 + threadIdx.x;
        bool ok = (r < cnt);
        slts[threadIdx.x] = ok ? g_slot[e * NTOK + r] : -1;
        gat[threadIdx.x]  = ok ? g_egate[e * NTOK + r] : 0.0f;
    }
    __syncthreads();
    gemm_core<2>(g_h + (size_t)e * NTOK * FF, w2 + (size_t)e * FF * DM,
                 b2 + e * DM, g_ys,
                 FF, DM, row0, blockIdx.x * BN, 0, FF, nullptr, slts, gat);
}

// ---------------- tensor-core attention (512 threads, cp.async double-buffered) ----------------
// Q1 != nullptr: Q operand = (Q+Q1+qb) * 0.125  (split-K partials + bias)
#define AQT   32
#define KT2   64
#define KSTR  68
#define VSTR  72
#define KVBUF (KT2 * VSTR)
#define SSTR  516
#define QF_ELEMS (2 * 8 * 32 * 4)
#define ATC_SMEM ((QF_ELEMS + 2 * KVBUF + AQT * SSTR) * 4)   // 111104 B

__global__ __launch_bounds__(512, 2) void attn_tc_kernel(
    const float* __restrict__ Q, const float* __restrict__ Q1,
    const float* __restrict__ qb,
    const float* __restrict__ Kk, const float* __restrict__ V,
    float* __restrict__ O)
{
    extern __shared__ float am[];
    uint32_t* Qf = (uint32_t*)am;
    float* KV = am + QF_ELEMS;
    float* S  = KV + 2 * KVBUF;

    const int q0  = blockIdx.x * AQT;
    const int h   = blockIdx.y;
    const int b   = blockIdx.z;
    const int tid = threadIdx.x;
    const int lane = tid & 31;
    const int wid  = tid >> 5;
    const int wm   = wid >> 3;
    const int wn   = wid & 7;
    const int g    = lane >> 2;
    const int tig  = lane & 3;

    const int lrow = tid >> 3;
    const int lc   = (tid & 7) * 8;
    const float* ksrc = Kk + ((size_t)(b * TT) + lrow) * DM + h * DH + lc;
    const float* vsrc = V  + ((size_t)(b * TT) + lrow) * DM + h * DH + lc;
    uint32_t kdst = smem_u32(KV) + (lrow * KSTR + lc) * 4;
    uint32_t vdst = smem_u32(KV) + (lrow * VSTR + lc) * 4;

#define ISSUE_K(bf_, kt_) do {                                         \
        const float* s_ = ksrc + (size_t)(kt_) * KT2 * DM;             \
        uint32_t d_ = kdst + (uint32_t)(bf_) * (KVBUF * 4);            \
        cp16(d_, s_, true); cp16(d_ + 16, s_ + 4, true);               \
    } while (0)
#define ISSUE_V(bf_, kt_) do {                                         \
        const float* s_ = vsrc + (size_t)(kt_) * KT2 * DM;             \
        uint32_t d_ = vdst + (uint32_t)(bf_) * (KVBUF * 4);            \
        cp16(d_, s_, true); cp16(d_ + 16, s_ + 4, true);               \
    } while (0)

    ISSUE_K(0, 0); CP_COMMIT;

    for (int i = tid; i < QF_ELEMS; i += 512) {
        int r     = i & 3;
        int lane_ = (i >> 2) & 31;
        int k8    = (i >> 7) & 7;
        int wmf   = i >> 10;
        int gg = lane_ >> 2, tt = lane_ & 3;
        int row = q0 + wmf * 16 + gg + (r & 1) * 8;
        int col = k8 * 8 + tt + (r >> 1) * 4;
        size_t idx = ((size_t)(b * TT + row)) * DM + h * DH + col;
        float v;
        if (Q1) v = (Q[idx] + Q1[idx] + qb[h * DH + col]) * 0.125f;
        else    v = Q[idx] * 0.125f;
        Qf[i] = __float_as_uint(v);
    }

    int buf = 0;
    for (int kt = 0; kt < TT / KT2; kt++) {
        const bool more = (kt + 1 < TT / KT2);
        if (more) { ISSUE_K(buf ^ 1, kt + 1); CP_COMMIT; }
        if (more) { CP_WAIT1; } else { CP_WAIT0; }
        __syncthreads();

        const float* Kb = KV + buf * KVBUF;
        float c[4] = {0.f, 0.f, 0.f, 0.f};
        #pragma unroll
        for (int k8 = 0; k8 < DH / 8; k8++) {
            uint32_t af[4];
            *(uint4*)af = *(const uint4*)(Qf + ((wm * 8 + k8) * 32 + lane) * 4);
            const uint32_t* bb = (const uint32_t*)(Kb + (wn * 8 + g) * KSTR + k8 * 8 + tig);
            uint32_t bf2[2] = { bb[0], bb[4] };
            mma8(c, af, bf2);
        }
        int col = kt * KT2 + wn * 8 + 2 * tig;
        float* s0 = S + (wm * 16 + g) * SSTR + col;
        float* s1 = S + (wm * 16 + g + 8) * SSTR + col;
        s0[0] = c[0]; s0[1] = c[1];
        s1[0] = c[2]; s1[1] = c[3];
        __syncthreads();
        buf ^= 1;
    }

    ISSUE_V(0, 0); CP_COMMIT;

    #pragma unroll
    for (int rr = 0; rr < 2; rr++) {
        int row = wid * 2 + rr;
        float* sr = S + row * SSTR;
        float m = -1e30f;
        for (int j = lane; j < TT; j += 32) m = fmaxf(m, sr[j]);
        #pragma unroll
        for (int o = 16; o; o >>= 1) m = fmaxf(m, __shfl_xor_sync(0xFFFFFFFFu, m, o));
        float sum = 0.0f;
        for (int j = lane; j < TT; j += 32) { float ev = __expf(sr[j] - m); sr[j] = ev; sum += ev; }
        #pragma unroll
        for (int o = 16; o; o >>= 1) sum += __shfl_xor_sync(0xFFFFFFFFu, sum, o);
        float inv = 1.0f / sum;
        for (int j = lane; j < TT; j += 32) sr[j] = sr[j] * inv;
    }

    float acc[4] = {0.f, 0.f, 0.f, 0.f};
    buf = 0;
    for (int vt = 0; vt < TT / KT2; vt++) {
        const bool more = (vt + 1 < TT / KT2);
        if (more) { ISSUE_V(buf ^ 1, vt + 1); CP_COMMIT; }
        if (more) { CP_WAIT1; } else { CP_WAIT0; }
        __syncthreads();

        const float* Vb = KV + buf * KVBUF;
        #pragma unroll
        for (int k8 = 0; k8 < KT2 / 8; k8++) {
            uint32_t af[4];
            const uint32_t* ab = (const uint32_t*)(S + (wm * 16 + g) * SSTR + vt * KT2 + k8 * 8 + tig);
            af[0] = ab[0]; af[1] = ab[8 * SSTR]; af[2] = ab[4]; af[3] = ab[8 * SSTR + 4];
            const uint32_t* bb = (const uint32_t*)(Vb + (k8 * 8 + tig) * VSTR + wn * 8 + g);
            uint32_t bf2[2] = { bb[0], bb[4 * VSTR] };
            mma8(acc, af, bf2);
        }
        __syncthreads();
        buf ^= 1;
    }
#undef ISSUE_K
#undef ISSUE_V

    {
        int col = h * DH + wn * 8 + 2 * tig;
        size_t r0 = (size_t)(b * TT + q0 + wm * 16 + g) * DM + col;
        size_t r1 = (size_t)(b * TT + q0 + wm * 16 + g + 8) * DM + col;
        O[r0]     = acc[0]; O[r0 + 1] = acc[1];
        O[r1]     = acc[2]; O[r1 + 1] = acc[3];
    }
}

// ---------------- add(2 partials + bias) + layernorm ----------------
__global__ __launch_bounds__(256) void add_ln2_kernel(
    const float* __restrict__ x0, const float* __restrict__ x1,
    const float* __restrict__ xb, const float* __restrict__ r,
    const float* __restrict__ g, const float* __restrict__ be,
    float* __restrict__ out)
{
    __shared__ float red[32];
    __shared__ float s_mean, s_rstd;
    int row = blockIdx.x, tid = threadIdx.x;
    const float* p0 = x0 + (size_t)row * DM;
    const float* p1 = x1 + (size_t)row * DM;
    const float* rp = r + (size_t)row * DM;
    float v[4]; float sum = 0.0f;
    #pragma unroll
    for (int i = 0; i < 4; i++) {
        int idx = tid + i * 256;
        v[i] = (p0[idx] + p1[idx] + xb[idx]) + rp[idx];
        sum += v[i];
    }
    sum = block_reduce_sum(sum, red);
    if (tid == 0) s_mean = sum * (1.0f / DM);
    __syncthreads();
    float mean = s_mean, vs = 0.0f;
    #pragma unroll
    for (int i = 0; i < 4; i++) { float dv = v[i] - mean; vs += dv * dv; }
    vs = block_reduce_sum(vs, red);
    if (tid == 0) s_rstd = rsqrtf(vs * (1.0f / DM) + EPSL);
    __syncthreads();
    float rs = s_rstd;
    #pragma unroll
    for (int i = 0; i < 4; i++) {
        int idx = tid + i * 256;
        out[(size_t)row * DM + idx] = (v[i] - mean) * rs * g[idx] + be[idx];
    }
}

// ---------------- add(2 partials + bias) + layernorm + fused router (LN2) ----------------
__global__ __launch_bounds__(256) void add_ln2_router_kernel(
    const float* __restrict__ x0, const float* __restrict__ x1,
    const float* __restrict__ xb, const float* __restrict__ r,
    const float* __restrict__ g, const float* __restrict__ be,
    float* __restrict__ out,
    const float* __restrict__ rw, const float* __restrict__ rb)
{
    __shared__ float red[32];
    __shared__ float s_mean, s_rstd;
    __shared__ float logits[EE];
    int row = blockIdx.x, tid = threadIdx.x;
    const float* p0 = x0 + (size_t)row * DM;
    const float* p1 = x1 + (size_t)row * DM;
    const float* rp = r + (size_t)row * DM;
    float v[4]; float sum = 0.0f;
    #pragma unroll
    for (int i = 0; i < 4; i++) {
        int idx = tid + i * 256;
        v[i] = (p0[idx] + p1[idx] + xb[idx]) + rp[idx];
        sum += v[i];
    }
    sum = block_reduce_sum(sum, red);
    if (tid == 0) s_mean = sum * (1.0f / DM);
    __syncthreads();
    float mean = s_mean, vs = 0.0f;
    #pragma unroll
    for (int i = 0; i < 4; i++) { float dv = v[i] - mean; vs += dv * dv; }
    vs = block_reduce_sum(vs, red);
    if (tid == 0) s_rstd = rsqrtf(vs * (1.0f / DM) + EPSL);
    __syncthreads();
    float rs = s_rstd;
    #pragma unroll
    for (int i = 0; i < 4; i++) {
        int idx = tid + i * 256;
        out[(size_t)row * DM + idx] = (v[i] - mean) * rs * g[idx] + be[idx];
    }
    __syncthreads();

    // ---- router body (identical summation order to original router) ----
    int lane = tid & 31, w = tid >> 5;
    const float* op = out + (size_t)row * DM;
    float acc = 0.0f;
    for (int d = lane; d < DM; d += 32) acc += op[d] * rw[d * EE + w];
    #pragma unroll
    for (int o = 16; o; o >>= 1) acc += __shfl_xor_sync(0xFFFFFFFFu, acc, o);
    if (lane == 0) logits[w] = acc + rb[w];
    __syncthreads();
    if (tid == 0) {
        int t = row;
        float m = logits[0];
        #pragma unroll
        for (int e = 1; e < EE; e++) m = fmaxf(m, logits[e]);
        float p[EE], sm = 0.0f;
        #pragma unroll
        for (int e = 0; e < EE; e++) { p[e] = __expf(logits[e] - m); sm += p[e]; }
        float inv = 1.0f / sm;
        #pragma unroll
        for (int e = 0; e < EE; e++) { p[e] *= inv; atomicAdd(&g_imp[e], p[e]); }
        int i0 = 0;
        #pragma unroll
        for (int e = 1; e < EE; e++) if (p[e] > p[i0]) i0 = e;
        int i1 = (i0 == 0) ? 1 : 0;
        #pragma unroll
        for (int e = 0; e < EE; e++) if (e != i0 && p[e] > p[i1]) i1 = e;
        float g0 = p[i0], g1 = p[i1], gs = 1.0f / (g0 + g1);
        g0 *= gs; g1 *= gs;
        int pos = atomicAdd(&g_ecnt[i0], 1);
        g_elist[i0 * NTOK + pos] = t; g_egate[i0 * NTOK + pos] = g0;
        g_slot[i0 * NTOK + pos] = 2 * t;
        pos = atomicAdd(&g_ecnt[i1], 1);
        g_elist[i1 * NTOK + pos] = t; g_egate[i1 * NTOK + pos] = g1;
        g_slot[i1 * NTOK + pos] = 2 * t + 1;
    }
}

// ---------------- final add + layernorm over expert slots (+ lb loss) ----------------
__global__ __launch_bounds__(256) void add_ln_moe_kernel(
    const float* __restrict__ r, const float* __restrict__ g,
    const float* __restrict__ be, float* __restrict__ out,
    float* __restrict__ out_lb)
{
    __shared__ float red[32];
    __shared__ float s_mean, s_rstd;
    int row = blockIdx.x, tid = threadIdx.x;
    const float* y0 = g_ys + (size_t)(row * 2) * DM;
    const float* y1 = y0 + DM;
    const float* rp = r + (size_t)row * DM;
    float v[4]; float sum = 0.0f;
    #pragma unroll
    for (int i = 0; i < 4; i++) {
        int idx = tid + i * 256;
        v[i] = y0[idx] + y1[idx] + rp[idx];
        sum += v[i];
    }
    sum = block_reduce_sum(sum, red);
    if (tid == 0) s_mean = sum * (1.0f / DM);
    __syncthreads();
    float mean = s_mean, vs = 0.0f;
    #pragma unroll
    for (int i = 0; i < 4; i++) { float dv = v[i] - mean; vs += dv * dv; }
    vs = block_reduce_sum(vs, red);
    if (tid == 0) s_rstd = rsqrtf(vs * (1.0f / DM) + EPSL);
    __syncthreads();
    float rs = s_rstd;
    #pragma unroll
    for (int i = 0; i < 4; i++) {
        int idx = tid + i * 256;
        out[(size_t)row * DM + idx] = (v[i] - mean) * rs * g[idx] + be[idx];
    }
    if (row == 0 && tid == 0 && out_lb) {
        float lb = 0.0f;
        #pragma unroll
        for (int e = 0; e < EE; e++)
            lb += ((float)g_ecnt[e] / (float)(NTOK * 2)) * (g_imp[e] / (float)NTOK);
        out_lb[0] = (float)EE * lb;
    }
}

// ---------------- host launcher ----------------
extern "C" void kernel_launch(void* const* d_in, const int* in_sizes, int n_in,
                              void* d_out, int out_size)
{
    const float* tgt = (const float*)d_in[0];
    const float* mem = (const float*)d_in[1];
    const float *sa_wq, *sa_wk, *sa_wv, *sa_wo, *ca_wq, *ca_wk, *ca_wv, *ca_wo;
    const float *sa_bq, *sa_bk, *sa_bv, *sa_bo, *ca_bq, *ca_bk, *ca_bv, *ca_bo;
    const float *ln1g, *ln1b, *ln2g, *ln2b, *ln3g, *ln3b, *rw, *rb, *w1, *b1, *w2, *b2;

    if (in_sizes[5] == DM * DM) {
        sa_wq = (const float*)d_in[2];  sa_wk = (const float*)d_in[3];
        sa_wv = (const float*)d_in[4];  sa_wo = (const float*)d_in[5];
        ca_wq = (const float*)d_in[6];  ca_wk = (const float*)d_in[7];
        ca_wv = (const float*)d_in[8];  ca_wo = (const float*)d_in[9];
        sa_bq = (const float*)d_in[10]; sa_bk = (const float*)d_in[11];
        sa_bv = (const float*)d_in[12]; sa_bo = (const float*)d_in[13];
        ca_bq = (const float*)d_in[14]; ca_bk = (const float*)d_in[15];
        ca_bv = (const float*)d_in[16]; ca_bo = (const float*)d_in[17];
        ln1g = (const float*)d_in[18]; ln2g = (const float*)d_in[19]; ln3g = (const float*)d_in[20];
        ln1b = (const float*)d_in[21]; ln2b = (const float*)d_in[22]; ln3b = (const float*)d_in[23];
    } else {
        sa_wq = (const float*)d_in[2];  sa_wk = (const float*)d_in[3];
        sa_wv = (const float*)d_in[4];
        sa_bq = (const float*)d_in[5];  sa_bk = (const float*)d_in[6];
        sa_bv = (const float*)d_in[7];
        sa_wo = (const float*)d_in[8];  sa_bo = (const float*)d_in[9];
        ca_wq = (const float*)d_in[10]; ca_wk = (const float*)d_in[11];
        ca_wv = (const float*)d_in[12];
        ca_bq = (const float*)d_in[13]; ca_bk = (const float*)d_in[14];
        ca_bv = (const float*)d_in[15];
        ca_wo = (const float*)d_in[16]; ca_bo = (const float*)d_in[17];
        ln1g = (const float*)d_in[18]; ln1b = (const float*)d_in[19];
        ln2g = (const float*)d_in[20]; ln2b = (const float*)d_in[21];
        ln3g = (const float*)d_in[22]; ln3b = (const float*)d_in[23];
    }
    rw = (const float*)d_in[24]; rb = (const float*)d_in[25];
    w1 = (const float*)d_in[26]; b1 = (const float*)d_in[27];
    w2 = (const float*)d_in[28]; b2 = (const float*)d_in[29];

    float *q, *k, *v, *k2, *v2, *ctx, *attn, *ps, *t1, *t2;
    cudaGetSymbolAddress((void**)&q,    g_q);
    cudaGetSymbolAddress((void**)&k,    g_k);
    cudaGetSymbolAddress((void**)&v,    g_v);
    cudaGetSymbolAddress((void**)&k2,   g_k2);
    cudaGetSymbolAddress((void**)&v2,   g_v2);
    cudaGetSymbolAddress((void**)&ctx,  g_ctx);
    cudaGetSymbolAddress((void**)&attn, g_attn);
    cudaGetSymbolAddress((void**)&ps,   g_ps);
    cudaGetSymbolAddress((void**)&t1,   g_t1);
    cudaGetSymbolAddress((void**)&t2,   g_t2);

    float* out = (float*)d_out;

    cudaFuncSetAttribute(proj_splitk_kernel, cudaFuncAttributeMaxDynamicSharedMemorySize, GEMM_SMEM);
    cudaFuncSetAttribute(proj_qkv5_kernel,   cudaFuncAttributeMaxDynamicSharedMemorySize, GEMM_SMEM);
    cudaFuncSetAttribute(moe1_kernel,        cudaFuncAttributeMaxDynamicSharedMemorySize, GEMM_SMEM);
    cudaFuncSetAttribute(moe2_kernel,        cudaFuncAttributeMaxDynamicSharedMemorySize, GEMM_SMEM);
    cudaFuncSetAttribute(attn_tc_kernel,     cudaFuncAttributeMaxDynamicSharedMemorySize, ATC_SMEM);

    dim3 gQKV5(DM / BN, NTOK / BM, 5);     // (8, 16, 5)
    dim3 gSK  (DM / BN, NTOK / BM, 2);     // (8, 16, 2): split-K halves
    dim3 gAttn(TT / AQT, HH, BB);          // (16, 16, 4)
    dim3 gMoe1(FF / BN, NTOK / BM, EE);
    dim3 gMoe2(DM / BN, NTOK / BM, EE);

    zero_small_kernel<<<1, 32>>>();

    // ---- input-dependent projections (sa QKV + ca KV), raw fp32 operands ----
    proj_qkv5_kernel<<<gQKV5, 256, GEMM_SMEM>>>(
        tgt, tgt, tgt, mem, mem,
        sa_wq, sa_wk, sa_wv, ca_wk, ca_wv,
        sa_bq, sa_bk, sa_bv, ca_bk, ca_bv,
        q, k, v, k2, v2, DM, DM);

    // ---- self attention ----
    attn_tc_kernel<<<gAttn, 512, ATC_SMEM>>>(q, nullptr, nullptr, k, v, ctx);
    proj_splitk_kernel<<<gSK, 256, GEMM_SMEM>>>(ctx, sa_wo, attn, ps);
    add_ln2_kernel<<<NTOK, 256>>>(attn, ps, sa_bo, tgt, ln1g, ln1b, t1);

    // ---- cross attention ----
    proj_splitk_kernel<<<gSK, 256, GEMM_SMEM>>>(t1, ca_wq, q, ps);
    attn_tc_kernel<<<gAttn, 512, ATC_SMEM>>>(q, ps, ca_bq, k2, v2, ctx);
    proj_splitk_kernel<<<gSK, 256, GEMM_SMEM>>>(ctx, ca_wo, attn, ps);
    add_ln2_router_kernel<<<NTOK, 256>>>(attn, ps, ca_bo, t1, ln2g, ln2b, t2, rw, rb);

    // ---- MoE (sparse top-2, slot-based scatter) ----
    moe1_kernel<<<gMoe1, 256, GEMM_SMEM>>>(t2, w1, b1);
    moe2_kernel<<<gMoe2, 256, GEMM_SMEM>>>(w2, b2);
    add_ln_moe_kernel<<<NTOK, 256>>>(t2, ln3g, ln3b, out,
        (out_size > NTOK * DM) ? (out + (size_t)NTOK * DM) : nullptr);
}